// round 11
// baseline (speedup 1.0000x reference)
#include <cuda_runtime.h>
#include <cuda_fp16.h>
#include <cstdint>
#include <math.h>

// Problem constants (fixed instance)
#define NN 131072   // nodes
#define DD 128      // feature dim
#define GG 2048     // graphs
#define HH 512      // hidden
#define H4 2048     // 4*H
#define K2 1024     // output q_star stride (2H)
#define KA 640      // GEMM K stride: [h(512) | s(128)]

// ---------------- scratch (static device globals; no allocation) -------------
__device__ __half d_Wch[H4 * KA];      // rows permuted nj=4k+gate: [Wc_h | Wrm]
__device__ float d_bias4f[H4];         // permuted bias: [k*4+gate]
__device__ float d_gbias4f[H4];        // permuted bias + h0 contribution (t=1)
__device__ float d_vb4f[H4];           // permuted vb = Wih_r @ b_m
__device__ float d_Wmt[DD * HH];       // W_m transposed
__device__ __half d_xh[GG * KA];       // fp16 A operand: [h | s] per graph
__device__ __half d_fh[NN * DD];       // fp16 features
__device__ float d_c[GG * HH];         // LSTM cell state (t=1 -> t=2)
__device__ float d_hf[GG * HH];        // fp32 h (GEMM epilogue -> u_beta)
__device__ float d_h0[HH];             // shared h after t=0
__device__ float d_c0[HH];             // shared c after t=0
__device__ float d_u0[DD];             // shared u after t=0
__device__ float d_beta0[1];           // shared beta after t=0
__device__ float d_u[GG * DD];         // u_g = W_m^T h_g
__device__ float d_beta[GG];           // b_m . h_g
__device__ float d_s[GG * DD];         // s_g fp32 (final compute_r)
__device__ float d_tg[GG];             // exp_sum/(exp_sum+eps)
__device__ int   d_start[GG + 1];      // segment offsets

__device__ __forceinline__ float fsig(float x) {
    return __fdividef(1.0f, 1.0f + __expf(-x));
}
__device__ __forceinline__ float ftanh(float x) {
    return __fdividef(2.0f, 1.0f + __expf(-2.0f * x)) - 1.0f;
}
__device__ __forceinline__ int njperm(int j) { return 4 * (j & 511) + (j >> 9); }

// ---------------- prep_all: everything independent, one launch ---------------
#define B_FEAT 8192
#define B_WCH  4096      // H4*512/256
#define B_WRM  128       // 16 j rows per block
#define B_WMT  256
#define B_B4   2
#define B_VB   256       // 8 j per block (one warp each)
#define B_OFF  9
#define PREP_BLOCKS (B_FEAT + B_WCH + B_WRM + B_WMT + B_B4 + B_VB + B_OFF + 1)

__global__ __launch_bounds__(256) void prep_all(
    const float* __restrict__ f, const float* __restrict__ W_ih,
    const float* __restrict__ W_hh, const float* __restrict__ b_ih,
    const float* __restrict__ b_hh, const float* __restrict__ W_m,
    const float* __restrict__ b_m, const int* __restrict__ gi) {
    int b = blockIdx.x;
    int tid = threadIdx.x;
    if (b < B_FEAT) {                       // features -> fp16
        int idx = b * 256 + tid;            // 1 thread = 8 floats
        const float4* f4 = (const float4*)f;
        float4 a = f4[idx * 2], bb = f4[idx * 2 + 1];
        __half2 h0 = __floats2half2_rn(a.x, a.y);
        __half2 h1 = __floats2half2_rn(a.z, a.w);
        __half2 h2 = __floats2half2_rn(bb.x, bb.y);
        __half2 h3 = __floats2half2_rn(bb.z, bb.w);
        uint4 packed;
        packed.x = *(uint32_t*)&h0; packed.y = *(uint32_t*)&h1;
        packed.z = *(uint32_t*)&h2; packed.w = *(uint32_t*)&h3;
        ((uint4*)d_fh)[idx] = packed;
        return;
    }
    b -= B_FEAT;
    if (b < B_WCH) {                        // Wc_h = W_ih[:, :512]+W_hh, permuted
        int idx = b * 256 + tid;            // j*512 + col
        int j = idx >> 9, col = idx & 511;
        float v = W_ih[(size_t)j * 1024 + col] + W_hh[(size_t)j * HH + col];
        d_Wch[(size_t)njperm(j) * KA + col] = __float2half(v);
        return;
    }
    b -= B_WCH;
    if (b < B_WRM) {                        // Wrm[j,d] = Wih_r[j,:] . W_m[:,d]
        int j0 = b * 16;
        int d = tid & 127, jh = tid >> 7;   // 2 j in parallel
#pragma unroll
        for (int jp = 0; jp < 8; jp++) {
            int j = j0 + jp * 2 + jh;
            const float* wr = W_ih + (size_t)j * 1024 + 512;
            float acc = 0.0f;
            for (int k = 0; k < HH; k++)
                acc += wr[k] * W_m[k * DD + d];
            d_Wch[(size_t)njperm(j) * KA + 512 + d] = __float2half(acc);
        }
        return;
    }
    b -= B_WRM;
    if (b < B_WMT) {                        // W_m transposed
        int idx = b * 256 + tid;
        int d = idx >> 9, k = idx & 511;
        d_Wmt[idx] = W_m[k * DD + d];
        return;
    }
    b -= B_WMT;
    if (b < B_B4) {                         // permuted bias float4 per k
        int k = b * 256 + tid;
        float4 v;
        v.x = b_ih[k] + b_hh[k];
        v.y = b_ih[HH + k] + b_hh[HH + k];
        v.z = b_ih[2 * HH + k] + b_hh[2 * HH + k];
        v.w = b_ih[3 * HH + k] + b_hh[3 * HH + k];
        ((float4*)d_bias4f)[k] = v;
        return;
    }
    b -= B_B4;
    if (b < B_VB) {                         // vb[j] = Wih_r[j,:] . b_m
        int w = tid >> 5, lane = tid & 31;
        int j = b * 8 + w;
        const float* wr = W_ih + (size_t)j * 1024 + 512;
        float p = 0.0f;
#pragma unroll
        for (int k = lane; k < HH; k += 32) p += wr[k] * b_m[k];
        p += __shfl_xor_sync(0xffffffffu, p, 16);
        p += __shfl_xor_sync(0xffffffffu, p, 8);
        p += __shfl_xor_sync(0xffffffffu, p, 4);
        p += __shfl_xor_sync(0xffffffffu, p, 2);
        p += __shfl_xor_sync(0xffffffffu, p, 1);
        if (lane == 0) d_vb4f[njperm(j)] = p;
        return;
    }
    b -= B_VB;
    if (b < B_OFF) {                        // segment offsets (sorted index)
        int g = b * 256 + tid;
        if (g > GG) return;
        int lo = 0, hi = NN;
        while (lo < hi) { int mid = (lo + hi) >> 1; if (gi[mid] < g) lo = mid + 1; else hi = mid; }
        d_start[g] = lo;
        return;
    }
    // ---- init0: t=0 shared h0/c0/u0/beta0 (gates = bias for every graph) ----
    {
        __shared__ float h_s[HH];
        __shared__ float br[256];
        float bsum = 0.0f;
#pragma unroll
        for (int q = 0; q < 2; q++) {
            int k = tid + q * 256;
            float big = b_ih[k] + b_hh[k];
            float bgg = b_ih[2 * HH + k] + b_hh[2 * HH + k];
            float bog = b_ih[3 * HH + k] + b_hh[3 * HH + k];
            float c = fsig(big) * ftanh(bgg);          // c_prev = 0
            float h = fsig(bog) * ftanh(c);
            h_s[k] = h;
            d_h0[k] = h;
            d_c0[k] = c;
            bsum += b_m[k] * h;
        }
        br[tid] = bsum;
        __syncthreads();
        if (tid < DD) {                     // u0[d] = sum_k W_m[k,d]*h0[k]
            float a = 0.0f;
            for (int k = 0; k < HH; k++) a += W_m[k * DD + tid] * h_s[k];
            d_u0[tid] = a;
        }
        for (int s = 128; s > 0; s >>= 1) {
            if (tid < s) br[tid] += br[tid + s];
            __syncthreads();
        }
        if (tid == 0) d_beta0[0] = br[0];
    }
}

// ------ gates GEMM (fp16 mma.sync m16n8k16) + fused LSTM epilogue ------------
// CTA 128(M) x 256(N), BK=32, double buffer, 512 threads / 16 warps,
// warp tile 64x32. Column c = gate (c&3) of hidden unit k=(c>>2).
// gates = A @ Wch^T + bias + tg(row) * vb(col); LSTM in epilogue.
#define SROWH 40
#define A_STGH (128 * SROWH)
#define B_STGH (256 * SROWH)
#define EPI_STRIDE 68
#define GEMM_SMEM (2 * 128 * EPI_STRIDE * 4 + 512)

__device__ __forceinline__ void cpa16(uint32_t daddr, const void* g) {
    asm volatile("cp.async.cg.shared.global [%0], [%1], 16;" :: "r"(daddr), "l"(g));
}

__device__ __forceinline__ void load_stage(uint32_t sA, uint32_t sB,
                                           int bm, int bn, int k0, int tid) {
    {
        int row = tid >> 2, c = tid & 3;
        cpa16(sA + (uint32_t)(row * SROWH + c * 8) * 2,
              d_xh + (size_t)(bm + row) * KA + k0 + c * 8);
    }
#pragma unroll
    for (int j = 0; j < 2; j++) {
        int b = tid + j * 512;
        int row = b >> 2, c = b & 3;
        cpa16(sB + (uint32_t)(row * SROWH + c * 8) * 2,
              d_Wch + (size_t)(bn + row) * KA + k0 + c * 8);
    }
    asm volatile("cp.async.commit_group;");
}

// FIRST=true : t=1 (KOFF=512,KLEN=128): gbias + shared c0, writes c,xh,hf
// FIRST=false: t=2 (KOFF=0,KLEN=640)  : bias + per-graph c,  writes hf,out
template <int KOFF, int KLEN, bool FIRST>
__global__ __launch_bounds__(512, 1) void gemm_lstm(float* __restrict__ out) {
    extern __shared__ __half smh[];
    __half* Abase = smh;
    __half* Bbase = smh + 2 * A_STGH;
    uint32_t sAu, sBu;
    {
        uint64_t t;
        asm("cvta.to.shared.u64 %0, %1;" : "=l"(t) : "l"(Abase));
        sAu = (uint32_t)t;
        asm("cvta.to.shared.u64 %0, %1;" : "=l"(t) : "l"(Bbase));
        sBu = (uint32_t)t;
    }
    const int tid = threadIdx.x, lane = tid & 31, warp = tid >> 5;
    const int wm = (warp & 1) * 64, wn = (warp >> 1) * 32;
    const int g = lane >> 2, t = lane & 3;
    const int bm = blockIdx.y * 128, bn = blockIdx.x * 256;

    float acc[4][4][4];
#pragma unroll
    for (int a = 0; a < 4; a++)
#pragma unroll
        for (int b = 0; b < 4; b++)
#pragma unroll
            for (int c = 0; c < 4; c++) acc[a][b][c] = 0.0f;

    load_stage(sAu, sBu, bm, bn, KOFF, tid);

    const int NIT = KLEN / 32;
    for (int it = 0; it < NIT; it++) {
        int buf = it & 1;
        if (it + 1 < NIT) {
            int nb = buf ^ 1;
            load_stage(sAu + nb * A_STGH * 2, sBu + nb * B_STGH * 2,
                       bm, bn, KOFF + (it + 1) * 32, tid);
            asm volatile("cp.async.wait_group 1;");
        } else {
            asm volatile("cp.async.wait_group 0;");
        }
        __syncthreads();

        const __half* Ab = Abase + buf * A_STGH;
        const __half* Bb = Bbase + buf * B_STGH;
#pragma unroll
        for (int kb = 0; kb < 32; kb += 16) {
            unsigned af[4][4], bf[4][2];
#pragma unroll
            for (int mi = 0; mi < 4; mi++) {
                const __half* ba = &Ab[(wm + mi * 16 + g) * SROWH + kb + 2 * t];
                af[mi][0] = *(const uint32_t*)(ba);
                af[mi][1] = *(const uint32_t*)(ba + 8 * SROWH);
                af[mi][2] = *(const uint32_t*)(ba + 8);
                af[mi][3] = *(const uint32_t*)(ba + 8 * SROWH + 8);
            }
#pragma unroll
            for (int ni = 0; ni < 4; ni++) {
                const __half* bb = &Bb[(wn + ni * 8 + g) * SROWH + kb + 2 * t];
                bf[ni][0] = *(const uint32_t*)(bb);
                bf[ni][1] = *(const uint32_t*)(bb + 8);
            }
#pragma unroll
            for (int mi = 0; mi < 4; mi++)
#pragma unroll
                for (int ni = 0; ni < 4; ni++)
                    asm volatile(
                        "mma.sync.aligned.m16n8k16.row.col.f32.f16.f16.f32 "
                        "{%0,%1,%2,%3}, {%4,%5,%6,%7}, {%8,%9}, {%0,%1,%2,%3};"
                        : "+f"(acc[mi][ni][0]), "+f"(acc[mi][ni][1]),
                          "+f"(acc[mi][ni][2]), "+f"(acc[mi][ni][3])
                        : "r"(af[mi][0]), "r"(af[mi][1]), "r"(af[mi][2]), "r"(af[mi][3]),
                          "r"(bf[ni][0]), "r"(bf[ni][1]));
        }
        __syncthreads();
    }

    // ---------------- fused LSTM epilogue ----------------
    float* hbuf = (float*)smh;                       // [128][EPI_STRIDE]
    float* cbuf = hbuf + 128 * EPI_STRIDE;
    float* tgs  = cbuf + 128 * EPI_STRIDE;           // [128]
    const int kb0 = bn >> 2;
    const float4* b4p = (const float4*)(FIRST ? d_gbias4f : d_bias4f);
    const float4* vb4p = (const float4*)d_vb4f;

    if (tid < 128) tgs[tid] = d_tg[bm + tid];
    if (!FIRST) {                                    // preload c tile, coalesced
        int r = tid >> 2, kh = (tid & 3) * 16;
        const float4* src = (const float4*)(d_c + (size_t)(bm + r) * HH + kb0 + kh);
#pragma unroll
        for (int j = 0; j < 4; j++) {
            float4 v = src[j];
            float* dst = &cbuf[r * EPI_STRIDE + kh + 4 * j];
            dst[0] = v.x; dst[1] = v.y; dst[2] = v.z; dst[3] = v.w;
        }
    }
    __syncthreads();

    {
        const int kwarp = (bn + wn) >> 2;
        const bool odd = t & 1;
        const int khalf = t >> 1;
#pragma unroll
        for (int ni = 0; ni < 4; ni++) {
            int k = kwarp + ni * 2 + khalf;
            float4 b4 = b4p[k];
            float4 v4 = vb4p[k];
            float blo = odd ? b4.z : b4.x;
            float bhi = odd ? b4.w : b4.y;
            float vlo = odd ? v4.z : v4.x;
            float vhi = odd ? v4.w : v4.y;
            float cp_sh = FIRST ? d_c0[k] : 0.0f;
            int klocal = k - kb0;
#pragma unroll
            for (int mi = 0; mi < 4; mi++) {
                int rbase = wm + mi * 16 + g;
                float tg0 = tgs[rbase];
                float tg1 = tgs[rbase + 8];
                float a0 = acc[mi][ni][0] + blo + tg0 * vlo;
                float a1 = acc[mi][ni][1] + bhi + tg0 * vhi;
                float a2 = acc[mi][ni][2] + blo + tg1 * vlo;
                float a3 = acc[mi][ni][3] + bhi + tg1 * vhi;
                float slo = odd ? a0 : a2;
                float shi = odd ? a1 : a3;
                float rlo = __shfl_xor_sync(0xffffffffu, slo, 1);
                float rhi = __shfl_xor_sync(0xffffffffu, shi, 1);
                float iv = odd ? rlo : a0;
                float fv = odd ? rhi : a1;
                float gv = odd ? a2 : rlo;
                float ov = odd ? a3 : rhi;
                int rlocal = rbase + (odd ? 8 : 0);
                float cp = FIRST ? cp_sh : cbuf[rlocal * EPI_STRIDE + klocal];
                float cn = fsig(fv) * cp + fsig(iv) * ftanh(gv);
                float h = fsig(ov) * ftanh(cn);
                hbuf[rlocal * EPI_STRIDE + klocal] = h;
                if (FIRST) cbuf[rlocal * EPI_STRIDE + klocal] = cn;
            }
        }
    }
    __syncthreads();

    {   // coalesced writeout of the 128x64 tile
        int r = tid >> 2, kh = (tid & 3) * 16;
        int row = bm + r;
        int kg = kb0 + kh;
#pragma unroll
        for (int j = 0; j < 4; j++) {
            const float* hsrc = &hbuf[r * EPI_STRIDE + kh + 4 * j];
            float4 v = make_float4(hsrc[0], hsrc[1], hsrc[2], hsrc[3]);
            *(float4*)(d_hf + (size_t)row * HH + kg + 4 * j) = v;
            if (FIRST) {
                __half2 p0 = __floats2half2_rn(v.x, v.y);
                __half2 p1 = __floats2half2_rn(v.z, v.w);
                uint2 u; u.x = *(uint32_t*)&p0; u.y = *(uint32_t*)&p1;
                *(uint2*)(d_xh + (size_t)row * KA + kg + 4 * j) = u;
                const float* csrc = &cbuf[r * EPI_STRIDE + kh + 4 * j];
                float4 cv = make_float4(csrc[0], csrc[1], csrc[2], csrc[3]);
                *(float4*)(d_c + (size_t)row * HH + kg + 4 * j) = cv;
            } else {
                *(float4*)(out + (size_t)row * K2 + kg + 4 * j) = v;
            }
        }
    }
}

// ------- u_beta: u_g = W_m^T h_g, beta_g = b_m . h_g (16 graphs / block) -----
__global__ __launch_bounds__(256) void u_beta(const float* __restrict__ W_m,
                                              const float* __restrict__ b_m) {
    __shared__ float h_s[16][HH];                      // 32 KB
    __shared__ float red[2][16][DD];                   // 16 KB
    int g0 = blockIdx.x * 16;
    int tid = threadIdx.x;

    const float4* src = (const float4*)(d_hf + (size_t)g0 * HH);
    float4* dst = (float4*)h_s;
#pragma unroll
    for (int j = 0; j < 8; j++) dst[tid + j * 256] = src[tid + j * 256];
    __syncthreads();

    {
        int d = tid & 127, kh = tid >> 7;
        int kb = kh * 256;
        float acc[16];
#pragma unroll
        for (int gg = 0; gg < 16; gg++) acc[gg] = 0.0f;
        for (int k = 0; k < 256; k += 2) {
            float w0 = W_m[(kb + k) * DD + d];
            float w1 = W_m[(kb + k + 1) * DD + d];
#pragma unroll
            for (int gg = 0; gg < 16; gg++) {
                float2 hv = *(const float2*)&h_s[gg][kb + k];
                acc[gg] += w0 * hv.x + w1 * hv.y;
            }
        }
#pragma unroll
        for (int gg = 0; gg < 16; gg++) red[kh][gg][d] = acc[gg];
    }
    __syncthreads();
#pragma unroll
    for (int j = 0; j < 8; j++) {
        int e = tid + j * 256;
        int gg = e >> 7, dd = e & 127;
        d_u[(g0 + gg) * DD + dd] = red[0][gg][dd] + red[1][gg][dd];
    }
    {
        int w = tid >> 5, lane = tid & 31;
#pragma unroll
        for (int j = 0; j < 2; j++) {
            int gg = w * 2 + j;
            float p = 0.0f;
            for (int k = lane; k < HH; k += 32) p += b_m[k] * h_s[gg][k];
            p += __shfl_xor_sync(0xffffffffu, p, 16);
            p += __shfl_xor_sync(0xffffffffu, p, 8);
            p += __shfl_xor_sync(0xffffffffu, p, 4);
            p += __shfl_xor_sync(0xffffffffu, p, 2);
            p += __shfl_xor_sync(0xffffffffu, p, 1);
            if (lane == 0) d_beta[g0 + gg] = p;
        }
    }
}

// ------- fused attention; blocks >= GG (t=0 launch only) compute gbias -------
__global__ __launch_bounds__(256) void attention_fused(int use_u0) {
    int g = blockIdx.x;
    int tid = threadIdx.x, lane = tid & 31, warp = tid >> 5;
    if (g >= GG) {
        // gbias4f[nj] = bias4f[nj] + h0 . Wch[nj, :512]   (2 nj per warp)
        int base = (g - GG) * 16 + warp * 2;
#pragma unroll
        for (int r = 0; r < 2; r++) {
            int nj = base + r;
            const __half2* w2 = (const __half2*)(d_Wch + (size_t)nj * KA);
            const float2* h02 = (const float2*)d_h0;
            float p = 0.0f;
#pragma unroll
            for (int i = lane; i < HH / 2; i += 32) {
                float2 wf = __half22float2(w2[i]);
                float2 hf = h02[i];
                p += wf.x * hf.x + wf.y * hf.y;
            }
            p += __shfl_xor_sync(0xffffffffu, p, 16);
            p += __shfl_xor_sync(0xffffffffu, p, 8);
            p += __shfl_xor_sync(0xffffffffu, p, 4);
            p += __shfl_xor_sync(0xffffffffu, p, 2);
            p += __shfl_xor_sync(0xffffffffu, p, 1);
            if (lane == 0) d_gbias4f[nj] = d_bias4f[nj] + p;
        }
        return;
    }
    int s0 = d_start[g], s1 = d_start[g + 1];
    __shared__ __align__(16) float u_s[128];
    __shared__ __align__(16) float wacc[8][128];
    __shared__ float wm_s[8], wS_s[8], fac_s[8];
    __shared__ float inv_s;

    if (tid < 128) u_s[tid] = use_u0 ? d_u0[tid] : d_u[g * DD + tid];
    float beta = use_u0 ? d_beta0[0] : d_beta[g];
    __syncthreads();

    float4 uv = ((const float4*)u_s)[lane];
    float m = -3.4e38f, S = 0.0f;
    float4 acc = make_float4(0.f, 0.f, 0.f, 0.f);

    for (int base = s0 + warp * 4; base < s1; base += 32) {
        float4 fv[4];
        float e[4];
#pragma unroll
        for (int j = 0; j < 4; j++) {
            int n = base + j;
            if (n < s1) {
                uint2 raw = *(const uint2*)(d_fh + (size_t)n * DD + lane * 4);
                float2 f01 = __half22float2(*(__half2*)&raw.x);
                float2 f23 = __half22float2(*(__half2*)&raw.y);
                fv[j] = make_float4(f01.x, f01.y, f23.x, f23.y);
            } else {
                fv[j] = make_float4(0.f, 0.f, 0.f, 0.f);
            }
            e[j] = fv[j].x * uv.x + fv[j].y * uv.y + fv[j].z * uv.z + fv[j].w * uv.w;
        }
#pragma unroll
        for (int j = 0; j < 4; j++) {
            e[j] += __shfl_xor_sync(0xffffffffu, e[j], 16);
            e[j] += __shfl_xor_sync(0xffffffffu, e[j], 8);
            e[j] += __shfl_xor_sync(0xffffffffu, e[j], 4);
            e[j] += __shfl_xor_sync(0xffffffffu, e[j], 2);
            e[j] += __shfl_xor_sync(0xffffffffu, e[j], 1);
        }
#pragma unroll
        for (int j = 0; j < 4; j++)
            e[j] = (base + j < s1) ? e[j] + beta : -3.0e38f;

        float m4 = fmaxf(fmaxf(e[0], e[1]), fmaxf(e[2], e[3]));
        float w0 = __expf(e[0] - m4), w1 = __expf(e[1] - m4);
        float w2 = __expf(e[2] - m4), w3 = __expf(e[3] - m4);
        float S4 = (w0 + w1) + (w2 + w3);
        float4 a4;
        a4.x = w0 * fv[0].x + w1 * fv[1].x + w2 * fv[2].x + w3 * fv[3].x;
        a4.y = w0 * fv[0].y + w1 * fv[1].y + w2 * fv[2].y + w3 * fv[3].y;
        a4.z = w0 * fv[0].z + w1 * fv[1].z + w2 * fv[2].z + w3 * fv[3].z;
        a4.w = w0 * fv[0].w + w1 * fv[1].w + w2 * fv[2].w + w3 * fv[3].w;

        float mn = fmaxf(m, m4);
        float al = __expf(m - mn);
        float bl = __expf(m4 - mn);
        S = S * al + S4 * bl;
        acc.x = acc.x * al + a4.x * bl;
        acc.y = acc.y * al + a4.y * bl;
        acc.z = acc.z * al + a4.z * bl;
        acc.w = acc.w * al + a4.w * bl;
        m = mn;
    }
    if (lane == 0) { wm_s[warp] = m; wS_s[warp] = S; }
    ((float4*)wacc[warp])[lane] = acc;
    __syncthreads();

    if (tid == 0) {
        float M = -3.4e38f;
#pragma unroll
        for (int w = 0; w < 8; w++)
            if (wS_s[w] > 0.0f) M = fmaxf(M, wm_s[w]);
        float Z = 0.0f;
#pragma unroll
        for (int w = 0; w < 8; w++) {
            float sc = (wS_s[w] > 0.0f) ? __expf(wm_s[w] - M) : 0.0f;
            fac_s[w] = sc;
            Z += sc * wS_s[w];
        }
        float inv = 1.0f / (Z + 1e-7f);
        inv_s = inv;
        d_tg[g] = Z * inv;
    }
    __syncthreads();

    if (tid < 128) {
        float inv = inv_s;
        float s = 0.0f;
#pragma unroll
        for (int w = 0; w < 8; w++) s += wacc[w][tid] * fac_s[w];
        s *= inv;
        d_s[g * DD + tid] = s;
        d_xh[(size_t)g * KA + 512 + tid] = __float2half(s);   // fp16 A operand
    }
}

// -------- final r output: r_g = W_m s_g + t_g b_m  (8 graphs / block) --------
__global__ __launch_bounds__(512) void compute_r(const float* __restrict__ b_m,
                                                 float* __restrict__ out) {
    int g0 = blockIdx.x * 8;
    int k = threadIdx.x;                              // 0..511
    __shared__ float ss[8][128];
    {
        int i = k;        ss[i >> 7][i & 127] = d_s[(g0 + (i >> 7)) * DD + (i & 127)];
        int i2 = k + 512; ss[i2 >> 7][i2 & 127] = d_s[(g0 + (i2 >> 7)) * DD + (i2 & 127)];
    }
    __syncthreads();
    float bm = b_m[k];
    float acc[8];
#pragma unroll
    for (int gg = 0; gg < 8; gg++) acc[gg] = d_tg[g0 + gg] * bm;
    for (int d = 0; d < DD; d++) {
        float w = d_Wmt[d * HH + k];
#pragma unroll
        for (int gg = 0; gg < 8; gg++) acc[gg] += w * ss[gg][d];
    }
#pragma unroll
    for (int gg = 0; gg < 8; gg++)
        out[(g0 + gg) * K2 + HH + k] = acc[gg];
}

// ------------------------------ launcher ------------------------------------
extern "C" void kernel_launch(void* const* d_in, const int* in_sizes, int n_in,
                              void* d_out, int out_size) {
    const float* features = (const float*)d_in[0];
    const int*   gi       = (const int*)d_in[1];
    const float* W_m      = (const float*)d_in[2];
    const float* b_m      = (const float*)d_in[3];
    const float* W_ih     = (const float*)d_in[4];
    const float* W_hh     = (const float*)d_in[5];
    const float* b_ih     = (const float*)d_in[6];
    const float* b_hh     = (const float*)d_in[7];
    float* out = (float*)d_out;

    cudaFuncSetAttribute(gemm_lstm<512, 128, true>,
                         cudaFuncAttributeMaxDynamicSharedMemorySize, GEMM_SMEM);
    cudaFuncSetAttribute(gemm_lstm<0, 640, false>,
                         cudaFuncAttributeMaxDynamicSharedMemorySize, GEMM_SMEM);

    prep_all<<<PREP_BLOCKS, 256>>>(features, W_ih, W_hh, b_ih, b_hh, W_m, b_m, gi);

    // t = 0: shared u0/beta0; extra blocks compute gbias
    attention_fused<<<GG + 128, 256>>>(1);

    // t = 1: K=128 GEMM over s0 only (h0 in gbias, t0*vb rank-1 in epilogue)
    gemm_lstm<512, 128, true><<<dim3(H4 / 256, GG / 128), 512, GEMM_SMEM>>>(out);
    u_beta<<<GG / 16, 256>>>(W_m, b_m);
    attention_fused<<<GG, 256>>>(0);

    // t = 2: K=640 GEMM over [h1 | s1]; epilogue writes final h to out
    gemm_lstm<0, 640, false><<<dim3(H4 / 256, GG / 128), 512, GEMM_SMEM>>>(out);
    u_beta<<<GG / 16, 256>>>(W_m, b_m);
    attention_fused<<<GG, 256>>>(0);
    compute_r<<<256, 512>>>(b_m, out);
}

// round 12
// speedup vs baseline: 1.5980x; 1.5980x over previous
#include <cuda_runtime.h>
#include <cuda_fp16.h>
#include <cstdint>
#include <math.h>

// Problem constants (fixed instance)
#define NN 131072   // nodes
#define DD 128      // feature dim
#define GG 2048     // graphs
#define HH 512      // hidden
#define H4 2048     // 4*H
#define K2 1024     // output q_star stride (2H)
#define KA 640      // GEMM K stride: [h(512) | s(128)]

// ---------------- scratch (static device globals; no allocation) -------------
__device__ __half d_Wch[H4 * KA];      // rows permuted nj=4k+gate: [Wc_h | Wrm]
__device__ float d_bias4f[H4];         // permuted bias: [k*4+gate]
__device__ float d_gbias4f[H4];        // permuted bias + h0 contribution (t=1)
__device__ float d_vb4f[H4];           // permuted vb = Wih_r @ b_m
__device__ float d_Wmt[DD * HH];       // W_m transposed
__device__ __half d_xh[GG * KA];       // fp16 A operand: [h | s] per graph
__device__ __half d_fh[NN * DD];       // fp16 features
__device__ float d_c[GG * HH];         // LSTM cell state (t=1 -> t=2)
__device__ float d_hf[GG * HH];        // fp32 h (GEMM epilogue -> u_beta)
__device__ float d_h0[HH];             // shared h after t=0
__device__ float d_c0[HH];             // shared c after t=0
__device__ float d_u0[DD];             // shared u after t=0
__device__ float d_beta0[1];           // shared beta after t=0
__device__ float d_u[GG * DD];         // u_g = W_m^T h_g
__device__ float d_beta[GG];           // b_m . h_g
__device__ float d_s[GG * DD];         // s_g fp32 (final compute_r)
__device__ float d_tg[GG];             // exp_sum/(exp_sum+eps)
__device__ int   d_start[GG + 1];      // segment offsets

__device__ __forceinline__ float fsig(float x) {
    return __fdividef(1.0f, 1.0f + __expf(-x));
}
__device__ __forceinline__ float ftanh(float x) {
    return __fdividef(2.0f, 1.0f + __expf(-2.0f * x)) - 1.0f;
}
__device__ __forceinline__ int njperm(int j) { return 4 * (j & 511) + (j >> 9); }

// ---------------- prep_all: everything independent, one launch ---------------
#define B_FEAT 8192
#define B_WCH  4096      // H4*512/256
#define B_WRM  128       // 16 j rows per block (smem staged)
#define B_WMT  256
#define B_B4   2
#define B_VB   256       // 8 j per block (one warp each)
#define B_OFF  9
#define PREP_BLOCKS (B_FEAT + B_WCH + B_WRM + B_WMT + B_B4 + B_VB + B_OFF + 1)
#define PREP_SMEM 49152

__global__ __launch_bounds__(256) void prep_all(
    const float* __restrict__ f, const float* __restrict__ W_ih,
    const float* __restrict__ W_hh, const float* __restrict__ b_ih,
    const float* __restrict__ b_hh, const float* __restrict__ W_m,
    const float* __restrict__ b_m, const int* __restrict__ gi) {
    extern __shared__ float sm[];
    int b = blockIdx.x;
    int tid = threadIdx.x;
    if (b < B_FEAT) {                       // features -> fp16
        int idx = b * 256 + tid;            // 1 thread = 8 floats
        const float4* f4 = (const float4*)f;
        float4 a = f4[idx * 2], bb = f4[idx * 2 + 1];
        __half2 h0 = __floats2half2_rn(a.x, a.y);
        __half2 h1 = __floats2half2_rn(a.z, a.w);
        __half2 h2 = __floats2half2_rn(bb.x, bb.y);
        __half2 h3 = __floats2half2_rn(bb.z, bb.w);
        uint4 packed;
        packed.x = *(uint32_t*)&h0; packed.y = *(uint32_t*)&h1;
        packed.z = *(uint32_t*)&h2; packed.w = *(uint32_t*)&h3;
        ((uint4*)d_fh)[idx] = packed;
        return;
    }
    b -= B_FEAT;
    if (b < B_WCH) {                        // Wc_h = W_ih[:, :512]+W_hh, permuted
        int idx = b * 256 + tid;            // j*512 + col
        int j = idx >> 9, col = idx & 511;
        float v = W_ih[(size_t)j * 1024 + col] + W_hh[(size_t)j * HH + col];
        d_Wch[(size_t)njperm(j) * KA + col] = __float2half(v);
        return;
    }
    b -= B_WCH;
    if (b < B_WRM) {                        // Wrm[j,d] = Wih_r[j,:] . W_m[:,d]
        float* wr_s = sm;                   // [16][512] = 32KB
        float* red  = sm + 8192;            // [2][16][128] = 16KB
        int j0 = b * 16;
        for (int idx = tid; idx < 16 * HH; idx += 256) {
            int jj = idx >> 9, k = idx & 511;
            wr_s[idx] = W_ih[(size_t)(j0 + jj) * 1024 + 512 + k];
        }
        __syncthreads();
        int d = tid & 127, kh = tid >> 7;
        int kb = kh * 256;
        float acc[16];
#pragma unroll
        for (int jj = 0; jj < 16; jj++) acc[jj] = 0.0f;
        for (int k = 0; k < 256; k++) {
            float w = W_m[(size_t)(kb + k) * DD + d];
#pragma unroll
            for (int jj = 0; jj < 16; jj++)
                acc[jj] += w * wr_s[jj * HH + kb + k];
        }
#pragma unroll
        for (int jj = 0; jj < 16; jj++) red[(kh * 16 + jj) * 128 + d] = acc[jj];
        __syncthreads();
#pragma unroll
        for (int q = 0; q < 8; q++) {
            int e = tid + q * 256;          // 2048 outputs
            int jj = e >> 7, dd = e & 127;
            float v = red[jj * 128 + dd] + red[(16 + jj) * 128 + dd];
            d_Wch[(size_t)njperm(j0 + jj) * KA + 512 + dd] = __float2half(v);
        }
        return;
    }
    b -= B_WRM;
    if (b < B_WMT) {                        // W_m transposed
        int idx = b * 256 + tid;
        int d = idx >> 9, k = idx & 511;
        d_Wmt[idx] = W_m[k * DD + d];
        return;
    }
    b -= B_WMT;
    if (b < B_B4) {                         // permuted bias float4 per k
        int k = b * 256 + tid;
        float4 v;
        v.x = b_ih[k] + b_hh[k];
        v.y = b_ih[HH + k] + b_hh[HH + k];
        v.z = b_ih[2 * HH + k] + b_hh[2 * HH + k];
        v.w = b_ih[3 * HH + k] + b_hh[3 * HH + k];
        ((float4*)d_bias4f)[k] = v;
        return;
    }
    b -= B_B4;
    if (b < B_VB) {                         // vb[j] = Wih_r[j,:] . b_m
        int w = tid >> 5, lane = tid & 31;
        int j = b * 8 + w;
        const float* wr = W_ih + (size_t)j * 1024 + 512;
        float p = 0.0f;
#pragma unroll
        for (int k = lane; k < HH; k += 32) p += wr[k] * b_m[k];
        p += __shfl_xor_sync(0xffffffffu, p, 16);
        p += __shfl_xor_sync(0xffffffffu, p, 8);
        p += __shfl_xor_sync(0xffffffffu, p, 4);
        p += __shfl_xor_sync(0xffffffffu, p, 2);
        p += __shfl_xor_sync(0xffffffffu, p, 1);
        if (lane == 0) d_vb4f[njperm(j)] = p;
        return;
    }
    b -= B_VB;
    if (b < B_OFF) {                        // segment offsets (sorted index)
        int g = b * 256 + tid;
        if (g > GG) return;
        int lo = 0, hi = NN;
        while (lo < hi) { int mid = (lo + hi) >> 1; if (gi[mid] < g) lo = mid + 1; else hi = mid; }
        d_start[g] = lo;
        return;
    }
    // ---- init0: t=0 shared h0/c0/u0/beta0 (gates = bias for every graph) ----
    {
        float* h_s = sm;                    // [512]
        float* br  = sm + 512;              // [256]
        float bsum = 0.0f;
#pragma unroll
        for (int q = 0; q < 2; q++) {
            int k = tid + q * 256;
            float big = b_ih[k] + b_hh[k];
            float bgg = b_ih[2 * HH + k] + b_hh[2 * HH + k];
            float bog = b_ih[3 * HH + k] + b_hh[3 * HH + k];
            float c = fsig(big) * ftanh(bgg);          // c_prev = 0
            float h = fsig(bog) * ftanh(c);
            h_s[k] = h;
            d_h0[k] = h;
            d_c0[k] = c;
            bsum += b_m[k] * h;
        }
        br[tid] = bsum;
        __syncthreads();
        if (tid < DD) {                     // u0[d] = sum_k W_m[k,d]*h0[k]
            float a = 0.0f;
            for (int k = 0; k < HH; k++) a += W_m[k * DD + tid] * h_s[k];
            d_u0[tid] = a;
        }
        for (int s = 128; s > 0; s >>= 1) {
            if (tid < s) br[tid] += br[tid + s];
            __syncthreads();
        }
        if (tid == 0) d_beta0[0] = br[0];
    }
}

// ------ gates GEMM (fp16 mma.sync m16n8k16) + fused LSTM epilogue ------------
// CTA 128(M) x 256(N), BK=32, double buffer, 512 threads / 16 warps,
// warp tile 64x32. Column c = gate (c&3) of hidden unit k=(c>>2).
// gates = A @ Wch^T + bias + tg(row) * vb(col); LSTM in epilogue.
#define SROWH 40
#define A_STGH (128 * SROWH)
#define B_STGH (256 * SROWH)
#define EPI_STRIDE 68
#define GEMM_SMEM (2 * 128 * EPI_STRIDE * 4 + 512)

__device__ __forceinline__ void cpa16(uint32_t daddr, const void* g) {
    asm volatile("cp.async.cg.shared.global [%0], [%1], 16;" :: "r"(daddr), "l"(g));
}

__device__ __forceinline__ void load_stage(uint32_t sA, uint32_t sB,
                                           int bm, int bn, int k0, int tid) {
    {
        int row = tid >> 2, c = tid & 3;
        cpa16(sA + (uint32_t)(row * SROWH + c * 8) * 2,
              d_xh + (size_t)(bm + row) * KA + k0 + c * 8);
    }
#pragma unroll
    for (int j = 0; j < 2; j++) {
        int b = tid + j * 512;
        int row = b >> 2, c = b & 3;
        cpa16(sB + (uint32_t)(row * SROWH + c * 8) * 2,
              d_Wch + (size_t)(bn + row) * KA + k0 + c * 8);
    }
    asm volatile("cp.async.commit_group;");
}

// FIRST=true : t=1 (KOFF=512,KLEN=128): gbias + shared c0, writes c,xh,hf
// FIRST=false: t=2 (KOFF=0,KLEN=640)  : bias + per-graph c,  writes hf,out
template <int KOFF, int KLEN, bool FIRST>
__global__ __launch_bounds__(512, 1) void gemm_lstm(float* __restrict__ out) {
    extern __shared__ __half smh[];
    __half* Abase = smh;
    __half* Bbase = smh + 2 * A_STGH;
    uint32_t sAu, sBu;
    {
        uint64_t t;
        asm("cvta.to.shared.u64 %0, %1;" : "=l"(t) : "l"(Abase));
        sAu = (uint32_t)t;
        asm("cvta.to.shared.u64 %0, %1;" : "=l"(t) : "l"(Bbase));
        sBu = (uint32_t)t;
    }
    const int tid = threadIdx.x, lane = tid & 31, warp = tid >> 5;
    const int wm = (warp & 1) * 64, wn = (warp >> 1) * 32;
    const int g = lane >> 2, t = lane & 3;
    const int bm = blockIdx.y * 128, bn = blockIdx.x * 256;

    float acc[4][4][4];
#pragma unroll
    for (int a = 0; a < 4; a++)
#pragma unroll
        for (int b = 0; b < 4; b++)
#pragma unroll
            for (int c = 0; c < 4; c++) acc[a][b][c] = 0.0f;

    load_stage(sAu, sBu, bm, bn, KOFF, tid);

    const int NIT = KLEN / 32;
    for (int it = 0; it < NIT; it++) {
        int buf = it & 1;
        if (it + 1 < NIT) {
            int nb = buf ^ 1;
            load_stage(sAu + nb * A_STGH * 2, sBu + nb * B_STGH * 2,
                       bm, bn, KOFF + (it + 1) * 32, tid);
            asm volatile("cp.async.wait_group 1;");
        } else {
            asm volatile("cp.async.wait_group 0;");
        }
        __syncthreads();

        const __half* Ab = Abase + buf * A_STGH;
        const __half* Bb = Bbase + buf * B_STGH;
#pragma unroll
        for (int kb = 0; kb < 32; kb += 16) {
            unsigned af[4][4], bf[4][2];
#pragma unroll
            for (int mi = 0; mi < 4; mi++) {
                const __half* ba = &Ab[(wm + mi * 16 + g) * SROWH + kb + 2 * t];
                af[mi][0] = *(const uint32_t*)(ba);
                af[mi][1] = *(const uint32_t*)(ba + 8 * SROWH);
                af[mi][2] = *(const uint32_t*)(ba + 8);
                af[mi][3] = *(const uint32_t*)(ba + 8 * SROWH + 8);
            }
#pragma unroll
            for (int ni = 0; ni < 4; ni++) {
                const __half* bb = &Bb[(wn + ni * 8 + g) * SROWH + kb + 2 * t];
                bf[ni][0] = *(const uint32_t*)(bb);
                bf[ni][1] = *(const uint32_t*)(bb + 8);
            }
#pragma unroll
            for (int mi = 0; mi < 4; mi++)
#pragma unroll
                for (int ni = 0; ni < 4; ni++)
                    asm volatile(
                        "mma.sync.aligned.m16n8k16.row.col.f32.f16.f16.f32 "
                        "{%0,%1,%2,%3}, {%4,%5,%6,%7}, {%8,%9}, {%0,%1,%2,%3};"
                        : "+f"(acc[mi][ni][0]), "+f"(acc[mi][ni][1]),
                          "+f"(acc[mi][ni][2]), "+f"(acc[mi][ni][3])
                        : "r"(af[mi][0]), "r"(af[mi][1]), "r"(af[mi][2]), "r"(af[mi][3]),
                          "r"(bf[ni][0]), "r"(bf[ni][1]));
        }
        __syncthreads();
    }

    // ---------------- fused LSTM epilogue ----------------
    float* hbuf = (float*)smh;                       // [128][EPI_STRIDE]
    float* cbuf = hbuf + 128 * EPI_STRIDE;
    float* tgs  = cbuf + 128 * EPI_STRIDE;           // [128]
    const int kb0 = bn >> 2;
    const float4* b4p = (const float4*)(FIRST ? d_gbias4f : d_bias4f);
    const float4* vb4p = (const float4*)d_vb4f;

    if (tid < 128) tgs[tid] = d_tg[bm + tid];
    if (!FIRST) {                                    // preload c tile, coalesced
        int r = tid >> 2, kh = (tid & 3) * 16;
        const float4* src = (const float4*)(d_c + (size_t)(bm + r) * HH + kb0 + kh);
#pragma unroll
        for (int j = 0; j < 4; j++) {
            float4 v = src[j];
            float* dst = &cbuf[r * EPI_STRIDE + kh + 4 * j];
            dst[0] = v.x; dst[1] = v.y; dst[2] = v.z; dst[3] = v.w;
        }
    }
    __syncthreads();

    {
        const int kwarp = (bn + wn) >> 2;
        const bool odd = t & 1;
        const int khalf = t >> 1;
#pragma unroll
        for (int ni = 0; ni < 4; ni++) {
            int k = kwarp + ni * 2 + khalf;
            float4 b4 = b4p[k];
            float4 v4 = vb4p[k];
            float blo = odd ? b4.z : b4.x;
            float bhi = odd ? b4.w : b4.y;
            float vlo = odd ? v4.z : v4.x;
            float vhi = odd ? v4.w : v4.y;
            float cp_sh = FIRST ? d_c0[k] : 0.0f;
            int klocal = k - kb0;
#pragma unroll
            for (int mi = 0; mi < 4; mi++) {
                int rbase = wm + mi * 16 + g;
                float tg0 = tgs[rbase];
                float tg1 = tgs[rbase + 8];
                float a0 = acc[mi][ni][0] + blo + tg0 * vlo;
                float a1 = acc[mi][ni][1] + bhi + tg0 * vhi;
                float a2 = acc[mi][ni][2] + blo + tg1 * vlo;
                float a3 = acc[mi][ni][3] + bhi + tg1 * vhi;
                float slo = odd ? a0 : a2;
                float shi = odd ? a1 : a3;
                float rlo = __shfl_xor_sync(0xffffffffu, slo, 1);
                float rhi = __shfl_xor_sync(0xffffffffu, shi, 1);
                float iv = odd ? rlo : a0;
                float fv = odd ? rhi : a1;
                float gv = odd ? a2 : rlo;
                float ov = odd ? a3 : rhi;
                int rlocal = rbase + (odd ? 8 : 0);
                float cp = FIRST ? cp_sh : cbuf[rlocal * EPI_STRIDE + klocal];
                float cn = fsig(fv) * cp + fsig(iv) * ftanh(gv);
                float h = fsig(ov) * ftanh(cn);
                hbuf[rlocal * EPI_STRIDE + klocal] = h;
                if (FIRST) cbuf[rlocal * EPI_STRIDE + klocal] = cn;
            }
        }
    }
    __syncthreads();

    {   // coalesced writeout of the 128x64 tile
        int r = tid >> 2, kh = (tid & 3) * 16;
        int row = bm + r;
        int kg = kb0 + kh;
#pragma unroll
        for (int j = 0; j < 4; j++) {
            const float* hsrc = &hbuf[r * EPI_STRIDE + kh + 4 * j];
            float4 v = make_float4(hsrc[0], hsrc[1], hsrc[2], hsrc[3]);
            *(float4*)(d_hf + (size_t)row * HH + kg + 4 * j) = v;
            if (FIRST) {
                __half2 p0 = __floats2half2_rn(v.x, v.y);
                __half2 p1 = __floats2half2_rn(v.z, v.w);
                uint2 u; u.x = *(uint32_t*)&p0; u.y = *(uint32_t*)&p1;
                *(uint2*)(d_xh + (size_t)row * KA + kg + 4 * j) = u;
                const float* csrc = &cbuf[r * EPI_STRIDE + kh + 4 * j];
                float4 cv = make_float4(csrc[0], csrc[1], csrc[2], csrc[3]);
                *(float4*)(d_c + (size_t)row * HH + kg + 4 * j) = cv;
            } else {
                *(float4*)(out + (size_t)row * K2 + kg + 4 * j) = v;
            }
        }
    }
}

// ---- u_beta: u = h @ W_m, beta = h . b_m.  16 graphs/block, 1024 threads ----
// k split 8 ways (tid>>7), d = tid&127; dynamic smem: h 32KB + red 64KB.
#define UB_SMEM (16 * HH * 4 + 8 * 16 * 128 * 4)
__global__ __launch_bounds__(1024) void u_beta(const float* __restrict__ W_m,
                                               const float* __restrict__ b_m) {
    extern __shared__ float usm[];
    float* h_s = usm;                      // [16][512]
    float* red = usm + 16 * HH;            // [8][16][128]
    int g0 = blockIdx.x * 16;
    int tid = threadIdx.x;

    const float4* src = (const float4*)(d_hf + (size_t)g0 * HH);
    float4* dst = (float4*)h_s;
#pragma unroll
    for (int j = 0; j < 2; j++) dst[tid + j * 1024] = src[tid + j * 1024];
    __syncthreads();

    {
        int d = tid & 127, kq = tid >> 7;  // 0..7
        int kb = kq * 64;
        float acc[16];
#pragma unroll
        for (int gg = 0; gg < 16; gg++) acc[gg] = 0.0f;
        for (int k = 0; k < 64; k += 2) {
            float w0 = W_m[(size_t)(kb + k) * DD + d];
            float w1 = W_m[(size_t)(kb + k + 1) * DD + d];
#pragma unroll
            for (int gg = 0; gg < 16; gg++) {
                float2 hv = *(const float2*)&h_s[gg * HH + kb + k];
                acc[gg] += w0 * hv.x + w1 * hv.y;
            }
        }
#pragma unroll
        for (int gg = 0; gg < 16; gg++) red[(kq * 16 + gg) * 128 + d] = acc[gg];
    }
    __syncthreads();
#pragma unroll
    for (int j = 0; j < 2; j++) {
        int e = tid + j * 1024;            // 2048 outputs
        int gg = e >> 7, dd = e & 127;
        float s = 0.0f;
#pragma unroll
        for (int q = 0; q < 8; q++) s += red[(q * 16 + gg) * 128 + dd];
        d_u[(g0 + gg) * DD + dd] = s;
    }
    {   // beta: warps 0..15, one graph each
        int w = tid >> 5, lane = tid & 31;
        if (w < 16) {
            float p = 0.0f;
#pragma unroll
            for (int k = lane; k < HH; k += 32) p += b_m[k] * h_s[w * HH + k];
            p += __shfl_xor_sync(0xffffffffu, p, 16);
            p += __shfl_xor_sync(0xffffffffu, p, 8);
            p += __shfl_xor_sync(0xffffffffu, p, 4);
            p += __shfl_xor_sync(0xffffffffu, p, 2);
            p += __shfl_xor_sync(0xffffffffu, p, 1);
            if (lane == 0) d_beta[g0 + w] = p;
        }
    }
}

// ------- fused attention; blocks >= GG (t=0 launch only) compute gbias -------
__global__ __launch_bounds__(256) void attention_fused(int use_u0) {
    int g = blockIdx.x;
    int tid = threadIdx.x, lane = tid & 31, warp = tid >> 5;
    if (g >= GG) {
        // gbias4f[nj] = bias4f[nj] + h0 . Wch[nj, :512]   (2 nj per warp)
        int base = (g - GG) * 16 + warp * 2;
#pragma unroll
        for (int r = 0; r < 2; r++) {
            int nj = base + r;
            const __half2* w2 = (const __half2*)(d_Wch + (size_t)nj * KA);
            const float2* h02 = (const float2*)d_h0;
            float p = 0.0f;
#pragma unroll
            for (int i = lane; i < HH / 2; i += 32) {
                float2 wf = __half22float2(w2[i]);
                float2 hf = h02[i];
                p += wf.x * hf.x + wf.y * hf.y;
            }
            p += __shfl_xor_sync(0xffffffffu, p, 16);
            p += __shfl_xor_sync(0xffffffffu, p, 8);
            p += __shfl_xor_sync(0xffffffffu, p, 4);
            p += __shfl_xor_sync(0xffffffffu, p, 2);
            p += __shfl_xor_sync(0xffffffffu, p, 1);
            if (lane == 0) d_gbias4f[nj] = d_bias4f[nj] + p;
        }
        return;
    }
    int s0 = d_start[g], s1 = d_start[g + 1];
    __shared__ __align__(16) float u_s[128];
    __shared__ __align__(16) float wacc[8][128];
    __shared__ float wm_s[8], wS_s[8], fac_s[8];
    __shared__ float inv_s;

    if (tid < 128) u_s[tid] = use_u0 ? d_u0[tid] : d_u[g * DD + tid];
    float beta = use_u0 ? d_beta0[0] : d_beta[g];
    __syncthreads();

    float4 uv = ((const float4*)u_s)[lane];
    float m = -3.4e38f, S = 0.0f;
    float4 acc = make_float4(0.f, 0.f, 0.f, 0.f);

    for (int base = s0 + warp * 4; base < s1; base += 32) {
        float4 fv[4];
        float e[4];
#pragma unroll
        for (int j = 0; j < 4; j++) {
            int n = base + j;
            if (n < s1) {
                uint2 raw = *(const uint2*)(d_fh + (size_t)n * DD + lane * 4);
                float2 f01 = __half22float2(*(__half2*)&raw.x);
                float2 f23 = __half22float2(*(__half2*)&raw.y);
                fv[j] = make_float4(f01.x, f01.y, f23.x, f23.y);
            } else {
                fv[j] = make_float4(0.f, 0.f, 0.f, 0.f);
            }
            e[j] = fv[j].x * uv.x + fv[j].y * uv.y + fv[j].z * uv.z + fv[j].w * uv.w;
        }
#pragma unroll
        for (int j = 0; j < 4; j++) {
            e[j] += __shfl_xor_sync(0xffffffffu, e[j], 16);
            e[j] += __shfl_xor_sync(0xffffffffu, e[j], 8);
            e[j] += __shfl_xor_sync(0xffffffffu, e[j], 4);
            e[j] += __shfl_xor_sync(0xffffffffu, e[j], 2);
            e[j] += __shfl_xor_sync(0xffffffffu, e[j], 1);
        }
#pragma unroll
        for (int j = 0; j < 4; j++)
            e[j] = (base + j < s1) ? e[j] + beta : -3.0e38f;

        float m4 = fmaxf(fmaxf(e[0], e[1]), fmaxf(e[2], e[3]));
        float w0 = __expf(e[0] - m4), w1 = __expf(e[1] - m4);
        float w2 = __expf(e[2] - m4), w3 = __expf(e[3] - m4);
        float S4 = (w0 + w1) + (w2 + w3);
        float4 a4;
        a4.x = w0 * fv[0].x + w1 * fv[1].x + w2 * fv[2].x + w3 * fv[3].x;
        a4.y = w0 * fv[0].y + w1 * fv[1].y + w2 * fv[2].y + w3 * fv[3].y;
        a4.z = w0 * fv[0].z + w1 * fv[1].z + w2 * fv[2].z + w3 * fv[3].z;
        a4.w = w0 * fv[0].w + w1 * fv[1].w + w2 * fv[2].w + w3 * fv[3].w;

        float mn = fmaxf(m, m4);
        float al = __expf(m - mn);
        float bl = __expf(m4 - mn);
        S = S * al + S4 * bl;
        acc.x = acc.x * al + a4.x * bl;
        acc.y = acc.y * al + a4.y * bl;
        acc.z = acc.z * al + a4.z * bl;
        acc.w = acc.w * al + a4.w * bl;
        m = mn;
    }
    if (lane == 0) { wm_s[warp] = m; wS_s[warp] = S; }
    ((float4*)wacc[warp])[lane] = acc;
    __syncthreads();

    if (tid == 0) {
        float M = -3.4e38f;
#pragma unroll
        for (int w = 0; w < 8; w++)
            if (wS_s[w] > 0.0f) M = fmaxf(M, wm_s[w]);
        float Z = 0.0f;
#pragma unroll
        for (int w = 0; w < 8; w++) {
            float sc = (wS_s[w] > 0.0f) ? __expf(wm_s[w] - M) : 0.0f;
            fac_s[w] = sc;
            Z += sc * wS_s[w];
        }
        float inv = 1.0f / (Z + 1e-7f);
        inv_s = inv;
        d_tg[g] = Z * inv;
    }
    __syncthreads();

    if (tid < 128) {
        float inv = inv_s;
        float s = 0.0f;
#pragma unroll
        for (int w = 0; w < 8; w++) s += wacc[w][tid] * fac_s[w];
        s *= inv;
        d_s[g * DD + tid] = s;
        d_xh[(size_t)g * KA + 512 + tid] = __float2half(s);   // fp16 A operand
    }
}

// -------- final r output: r_g = W_m s_g + t_g b_m  (8 graphs / block) --------
__global__ __launch_bounds__(512) void compute_r(const float* __restrict__ b_m,
                                                 float* __restrict__ out) {
    int g0 = blockIdx.x * 8;
    int k = threadIdx.x;                              // 0..511
    __shared__ float ss[8][128];
    {
        int i = k;        ss[i >> 7][i & 127] = d_s[(g0 + (i >> 7)) * DD + (i & 127)];
        int i2 = k + 512; ss[i2 >> 7][i2 & 127] = d_s[(g0 + (i2 >> 7)) * DD + (i2 & 127)];
    }
    __syncthreads();
    float bm = b_m[k];
    float acc[8];
#pragma unroll
    for (int gg = 0; gg < 8; gg++) acc[gg] = d_tg[g0 + gg] * bm;
    for (int d = 0; d < DD; d++) {
        float w = d_Wmt[d * HH + k];
#pragma unroll
        for (int gg = 0; gg < 8; gg++) acc[gg] += w * ss[gg][d];
    }
#pragma unroll
    for (int gg = 0; gg < 8; gg++)
        out[(g0 + gg) * K2 + HH + k] = acc[gg];
}

// ------------------------------ launcher ------------------------------------
extern "C" void kernel_launch(void* const* d_in, const int* in_sizes, int n_in,
                              void* d_out, int out_size) {
    const float* features = (const float*)d_in[0];
    const int*   gi       = (const int*)d_in[1];
    const float* W_m      = (const float*)d_in[2];
    const float* b_m      = (const float*)d_in[3];
    const float* W_ih     = (const float*)d_in[4];
    const float* W_hh     = (const float*)d_in[5];
    const float* b_ih     = (const float*)d_in[6];
    const float* b_hh     = (const float*)d_in[7];
    float* out = (float*)d_out;

    cudaFuncSetAttribute(gemm_lstm<512, 128, true>,
                         cudaFuncAttributeMaxDynamicSharedMemorySize, GEMM_SMEM);
    cudaFuncSetAttribute(gemm_lstm<0, 640, false>,
                         cudaFuncAttributeMaxDynamicSharedMemorySize, GEMM_SMEM);
    cudaFuncSetAttribute(u_beta,
                         cudaFuncAttributeMaxDynamicSharedMemorySize, UB_SMEM);

    prep_all<<<PREP_BLOCKS, 256, PREP_SMEM>>>(features, W_ih, W_hh, b_ih, b_hh,
                                              W_m, b_m, gi);

    // t = 0: shared u0/beta0; extra blocks compute gbias
    attention_fused<<<GG + 128, 256>>>(1);

    // t = 1: K=128 GEMM over s0 only (h0 in gbias, t0*vb rank-1 in epilogue)
    gemm_lstm<512, 128, true><<<dim3(H4 / 256, GG / 128), 512, GEMM_SMEM>>>(out);
    u_beta<<<GG / 16, 1024, UB_SMEM>>>(W_m, b_m);
    attention_fused<<<GG, 256>>>(0);

    // t = 2: K=640 GEMM over [h1 | s1]; epilogue writes final h to out
    gemm_lstm<0, 640, false><<<dim3(H4 / 256, GG / 128), 512, GEMM_SMEM>>>(out);
    u_beta<<<GG / 16, 1024, UB_SMEM>>>(W_m, b_m);
    attention_fused<<<GG, 256>>>(0);
    compute_r<<<256, 512>>>(b_m, out);
}

// round 14
// speedup vs baseline: 1.7907x; 1.1206x over previous
#include <cuda_runtime.h>
#include <cuda_fp16.h>
#include <cstdint>
#include <math.h>

// Problem constants (fixed instance)
#define NN 131072   // nodes
#define DD 128      // feature dim
#define GG 2048     // graphs
#define HH 512      // hidden
#define H4 2048     // 4*H
#define K2 1024     // output q_star stride (2H)
#define KA 640      // GEMM K stride: [h(512) | s(128)]

// ---------------- scratch (static device globals; no allocation) -------------
__device__ __half d_Wch[H4 * KA];      // rows permuted nj=4k+gate: [Wc_h | Wrm]
__device__ float d_bias4f[H4];         // permuted bias: [k*4+gate]
__device__ float d_gbias4f[H4];        // permuted bias + h0 contribution (t=1)
__device__ float d_vb4f[H4];           // permuted vb = Wih_r @ b_m
__device__ float d_Wmt[DD * HH];       // W_m transposed (fp32, compute_r)
__device__ __half d_Wmth[DD * HH];     // W_m transposed fp16 (epilogue u-mma)
__device__ __half d_xh[GG * KA];       // fp16 A operand: [h | s] per graph
__device__ __half d_fh[NN * DD];       // fp16 features
__device__ float d_c[GG * HH];         // LSTM cell state (t=1 -> t=2)
__device__ float d_h0[HH];             // shared h after t=0
__device__ float d_c0[HH];             // shared c after t=0
__device__ float d_u0[DD];             // shared u after t=0
__device__ float d_beta0[1];           // shared beta after t=0
__device__ float d_upart[8 * GG * DD]; // u partials per k-slice q
__device__ float d_bpart[8 * GG];      // beta partials per k-slice q
__device__ float d_s[GG * DD];         // s_g fp32 (final compute_r)
__device__ float d_tg[GG];             // exp_sum/(exp_sum+eps)
__device__ int   d_start[GG + 1];      // segment offsets

__device__ __forceinline__ float fsig(float x) {
    return __fdividef(1.0f, 1.0f + __expf(-x));
}
__device__ __forceinline__ float ftanh(float x) {
    return __fdividef(2.0f, 1.0f + __expf(-2.0f * x)) - 1.0f;
}
__device__ __forceinline__ int njperm(int j) { return 4 * (j & 511) + (j >> 9); }

// ---------------- prep_all: everything independent, one launch ---------------
#define B_FEAT 8192
#define B_WCH  4096
#define B_WRM  128
#define B_WMT  256
#define B_B4   2
#define B_VB   256
#define B_OFF  9
#define PREP_BLOCKS (B_FEAT + B_WCH + B_WRM + B_WMT + B_B4 + B_VB + B_OFF + 1)
#define PREP_SMEM 49152

__global__ __launch_bounds__(256) void prep_all(
    const float* __restrict__ f, const float* __restrict__ W_ih,
    const float* __restrict__ W_hh, const float* __restrict__ b_ih,
    const float* __restrict__ b_hh, const float* __restrict__ W_m,
    const float* __restrict__ b_m, const int* __restrict__ gi) {
    extern __shared__ float sm[];
    int b = blockIdx.x;
    int tid = threadIdx.x;
    if (b < B_FEAT) {                       // features -> fp16
        int idx = b * 256 + tid;
        const float4* f4 = (const float4*)f;
        float4 a = f4[idx * 2], bb = f4[idx * 2 + 1];
        __half2 h0 = __floats2half2_rn(a.x, a.y);
        __half2 h1 = __floats2half2_rn(a.z, a.w);
        __half2 h2 = __floats2half2_rn(bb.x, bb.y);
        __half2 h3 = __floats2half2_rn(bb.z, bb.w);
        uint4 packed;
        packed.x = *(uint32_t*)&h0; packed.y = *(uint32_t*)&h1;
        packed.z = *(uint32_t*)&h2; packed.w = *(uint32_t*)&h3;
        ((uint4*)d_fh)[idx] = packed;
        return;
    }
    b -= B_FEAT;
    if (b < B_WCH) {                        // Wc_h = W_ih[:, :512]+W_hh, permuted
        int idx = b * 256 + tid;
        int j = idx >> 9, col = idx & 511;
        float v = W_ih[(size_t)j * 1024 + col] + W_hh[(size_t)j * HH + col];
        d_Wch[(size_t)njperm(j) * KA + col] = __float2half(v);
        return;
    }
    b -= B_WCH;
    if (b < B_WRM) {                        // Wrm[j,d] = Wih_r[j,:] . W_m[:,d]
        float* wr_s = sm;                   // [16][512]
        float* red  = sm + 8192;            // [2][16][128]
        int j0 = b * 16;
        for (int idx = tid; idx < 16 * HH; idx += 256) {
            int jj = idx >> 9, k = idx & 511;
            wr_s[idx] = W_ih[(size_t)(j0 + jj) * 1024 + 512 + k];
        }
        __syncthreads();
        int d = tid & 127, kh = tid >> 7;
        int kb = kh * 256;
        float acc[16];
#pragma unroll
        for (int jj = 0; jj < 16; jj++) acc[jj] = 0.0f;
        for (int k = 0; k < 256; k++) {
            float w = W_m[(size_t)(kb + k) * DD + d];
#pragma unroll
            for (int jj = 0; jj < 16; jj++)
                acc[jj] += w * wr_s[jj * HH + kb + k];
        }
#pragma unroll
        for (int jj = 0; jj < 16; jj++) red[(kh * 16 + jj) * 128 + d] = acc[jj];
        __syncthreads();
#pragma unroll
        for (int q = 0; q < 8; q++) {
            int e = tid + q * 256;
            int jj = e >> 7, dd = e & 127;
            float v = red[jj * 128 + dd] + red[(16 + jj) * 128 + dd];
            d_Wch[(size_t)njperm(j0 + jj) * KA + 512 + dd] = __float2half(v);
        }
        return;
    }
    b -= B_WRM;
    if (b < B_WMT) {                        // W_m transposed fp32 + fp16
        int idx = b * 256 + tid;
        int d = idx >> 9, k = idx & 511;
        float v = W_m[k * DD + d];
        d_Wmt[idx] = v;
        d_Wmth[idx] = __float2half(v);
        return;
    }
    b -= B_WMT;
    if (b < B_B4) {                         // permuted bias float4 per k
        int k = b * 256 + tid;
        float4 v;
        v.x = b_ih[k] + b_hh[k];
        v.y = b_ih[HH + k] + b_hh[HH + k];
        v.z = b_ih[2 * HH + k] + b_hh[2 * HH + k];
        v.w = b_ih[3 * HH + k] + b_hh[3 * HH + k];
        ((float4*)d_bias4f)[k] = v;
        return;
    }
    b -= B_B4;
    if (b < B_VB) {                         // vb[j] = Wih_r[j,:] . b_m
        int w = tid >> 5, lane = tid & 31;
        int j = b * 8 + w;
        const float* wr = W_ih + (size_t)j * 1024 + 512;
        float p = 0.0f;
#pragma unroll
        for (int k = lane; k < HH; k += 32) p += wr[k] * b_m[k];
        p += __shfl_xor_sync(0xffffffffu, p, 16);
        p += __shfl_xor_sync(0xffffffffu, p, 8);
        p += __shfl_xor_sync(0xffffffffu, p, 4);
        p += __shfl_xor_sync(0xffffffffu, p, 2);
        p += __shfl_xor_sync(0xffffffffu, p, 1);
        if (lane == 0) d_vb4f[njperm(j)] = p;
        return;
    }
    b -= B_VB;
    if (b < B_OFF) {                        // segment offsets (sorted index)
        int g = b * 256 + tid;
        if (g > GG) return;
        int lo = 0, hi = NN;
        while (lo < hi) { int mid = (lo + hi) >> 1; if (gi[mid] < g) lo = mid + 1; else hi = mid; }
        d_start[g] = lo;
        return;
    }
    // ---- init0 ----
    {
        float* h_s = sm;
        float* br  = sm + 512;
        float bsum = 0.0f;
#pragma unroll
        for (int q = 0; q < 2; q++) {
            int k = tid + q * 256;
            float big = b_ih[k] + b_hh[k];
            float bgg = b_ih[2 * HH + k] + b_hh[2 * HH + k];
            float bog = b_ih[3 * HH + k] + b_hh[3 * HH + k];
            float c = fsig(big) * ftanh(bgg);
            float h = fsig(bog) * ftanh(c);
            h_s[k] = h;
            d_h0[k] = h;
            d_c0[k] = c;
            bsum += b_m[k] * h;
        }
        br[tid] = bsum;
        __syncthreads();
        if (tid < DD) {
            float a = 0.0f;
            for (int k = 0; k < HH; k++) a += W_m[k * DD + tid] * h_s[k];
            d_u0[tid] = a;
        }
        for (int s = 128; s > 0; s >>= 1) {
            if (tid < s) br[tid] += br[tid + s];
            __syncthreads();
        }
        if (tid == 0) d_beta0[0] = br[0];
    }
}

// ------ gates GEMM + fused LSTM + fused u/beta partial epilogue --------------
// CTA 128(M) x 256(N), BK=32, double buffer, 512 threads / 16 warps,
// warp tile 64x32. Column c = gate (c&3) of hidden unit k=(c>>2).
// Epilogue: LSTM cell; then upart[q] = h_tile(128x64k) @ Wmth(128d x 512k)^T
// with warp mapping wn2=(warp>>1)*16 (d<128!), bpart[q][g] = b_m[ks].h[g].
#define SROWH 40
#define A_STGH (128 * SROWH)
#define B_STGH (256 * SROWH)
#define EPI_STRIDE 68
#define HB_STRIDE 72
#define GEMM_SMEM (2 * 128 * EPI_STRIDE * 4 + 512 + 128 * HB_STRIDE * 2)

__device__ __forceinline__ void cpa16(uint32_t daddr, const void* g) {
    asm volatile("cp.async.cg.shared.global [%0], [%1], 16;" :: "r"(daddr), "l"(g));
}

__device__ __forceinline__ void load_stage(uint32_t sA, uint32_t sB,
                                           int bm, int bn, int k0, int tid) {
    {
        int row = tid >> 2, c = tid & 3;
        cpa16(sA + (uint32_t)(row * SROWH + c * 8) * 2,
              d_xh + (size_t)(bm + row) * KA + k0 + c * 8);
    }
#pragma unroll
    for (int j = 0; j < 2; j++) {
        int b = tid + j * 512;
        int row = b >> 2, c = b & 3;
        cpa16(sB + (uint32_t)(row * SROWH + c * 8) * 2,
              d_Wch + (size_t)(bn + row) * KA + k0 + c * 8);
    }
    asm volatile("cp.async.commit_group;");
}

template <int KOFF, int KLEN, bool FIRST>
__global__ __launch_bounds__(512, 1) void gemm_lstm(float* __restrict__ out,
                                                    const float* __restrict__ b_m) {
    extern __shared__ __half smh[];
    __half* Abase = smh;
    __half* Bbase = smh + 2 * A_STGH;
    uint32_t sAu, sBu;
    {
        uint64_t t;
        asm("cvta.to.shared.u64 %0, %1;" : "=l"(t) : "l"(Abase));
        sAu = (uint32_t)t;
        asm("cvta.to.shared.u64 %0, %1;" : "=l"(t) : "l"(Bbase));
        sBu = (uint32_t)t;
    }
    const int tid = threadIdx.x, lane = tid & 31, warp = tid >> 5;
    const int wm = (warp & 1) * 64, wn = (warp >> 1) * 32;
    const int g = lane >> 2, t = lane & 3;
    const int bm = blockIdx.y * 128, bn = blockIdx.x * 256;
    const int q = blockIdx.x;                        // k-slice index 0..7

    float acc[4][4][4];
#pragma unroll
    for (int a = 0; a < 4; a++)
#pragma unroll
        for (int b = 0; b < 4; b++)
#pragma unroll
            for (int c = 0; c < 4; c++) acc[a][b][c] = 0.0f;

    load_stage(sAu, sBu, bm, bn, KOFF, tid);

    const int NIT = KLEN / 32;
    for (int it = 0; it < NIT; it++) {
        int buf = it & 1;
        if (it + 1 < NIT) {
            int nb = buf ^ 1;
            load_stage(sAu + nb * A_STGH * 2, sBu + nb * B_STGH * 2,
                       bm, bn, KOFF + (it + 1) * 32, tid);
            asm volatile("cp.async.wait_group 1;");
        } else {
            asm volatile("cp.async.wait_group 0;");
        }
        __syncthreads();

        const __half* Ab = Abase + buf * A_STGH;
        const __half* Bb = Bbase + buf * B_STGH;
#pragma unroll
        for (int kb = 0; kb < 32; kb += 16) {
            unsigned af[4][4], bf[4][2];
#pragma unroll
            for (int mi = 0; mi < 4; mi++) {
                const __half* ba = &Ab[(wm + mi * 16 + g) * SROWH + kb + 2 * t];
                af[mi][0] = *(const uint32_t*)(ba);
                af[mi][1] = *(const uint32_t*)(ba + 8 * SROWH);
                af[mi][2] = *(const uint32_t*)(ba + 8);
                af[mi][3] = *(const uint32_t*)(ba + 8 * SROWH + 8);
            }
#pragma unroll
            for (int ni = 0; ni < 4; ni++) {
                const __half* bb = &Bb[(wn + ni * 8 + g) * SROWH + kb + 2 * t];
                bf[ni][0] = *(const uint32_t*)(bb);
                bf[ni][1] = *(const uint32_t*)(bb + 8);
            }
#pragma unroll
            for (int mi = 0; mi < 4; mi++)
#pragma unroll
                for (int ni = 0; ni < 4; ni++)
                    asm volatile(
                        "mma.sync.aligned.m16n8k16.row.col.f32.f16.f16.f32 "
                        "{%0,%1,%2,%3}, {%4,%5,%6,%7}, {%8,%9}, {%0,%1,%2,%3};"
                        : "+f"(acc[mi][ni][0]), "+f"(acc[mi][ni][1]),
                          "+f"(acc[mi][ni][2]), "+f"(acc[mi][ni][3])
                        : "r"(af[mi][0]), "r"(af[mi][1]), "r"(af[mi][2]), "r"(af[mi][3]),
                          "r"(bf[ni][0]), "r"(bf[ni][1]));
        }
        __syncthreads();
    }

    // ---------------- fused LSTM epilogue ----------------
    float* hbuf = (float*)smh;                       // [128][EPI_STRIDE] fp32 h
    float* cbuf = hbuf + 128 * EPI_STRIDE;           // [128][EPI_STRIDE] c
    float* tgs  = cbuf + 128 * EPI_STRIDE;           // [128]
    __half* hb16 = (__half*)(tgs + 128);             // [128][HB_STRIDE] fp16 h
    const int kb0 = bn >> 2;                         // first k of CTA tile
    const float4* b4p = (const float4*)(FIRST ? d_gbias4f : d_bias4f);
    const float4* vb4p = (const float4*)d_vb4f;

    if (tid < 128) tgs[tid] = d_tg[bm + tid];
    if (!FIRST) {                                    // preload c tile, coalesced
        int r = tid >> 2, kh = (tid & 3) * 16;
        const float4* src = (const float4*)(d_c + (size_t)(bm + r) * HH + kb0 + kh);
#pragma unroll
        for (int j = 0; j < 4; j++) {
            float4 v = src[j];
            float* dst = &cbuf[r * EPI_STRIDE + kh + 4 * j];
            dst[0] = v.x; dst[1] = v.y; dst[2] = v.z; dst[3] = v.w;
        }
    }
    __syncthreads();

    {
        const int kwarp = (bn + wn) >> 2;
        const bool odd = t & 1;
        const int khalf = t >> 1;
#pragma unroll
        for (int ni = 0; ni < 4; ni++) {
            int k = kwarp + ni * 2 + khalf;
            float4 b4 = b4p[k];
            float4 v4 = vb4p[k];
            float blo = odd ? b4.z : b4.x;
            float bhi = odd ? b4.w : b4.y;
            float vlo = odd ? v4.z : v4.x;
            float vhi = odd ? v4.w : v4.y;
            float cp_sh = FIRST ? d_c0[k] : 0.0f;
            int klocal = k - kb0;
#pragma unroll
            for (int mi = 0; mi < 4; mi++) {
                int rbase = wm + mi * 16 + g;
                float tg0 = tgs[rbase];
                float tg1 = tgs[rbase + 8];
                float a0 = acc[mi][ni][0] + blo + tg0 * vlo;
                float a1 = acc[mi][ni][1] + bhi + tg0 * vhi;
                float a2 = acc[mi][ni][2] + blo + tg1 * vlo;
                float a3 = acc[mi][ni][3] + bhi + tg1 * vhi;
                float slo = odd ? a0 : a2;
                float shi = odd ? a1 : a3;
                float rlo = __shfl_xor_sync(0xffffffffu, slo, 1);
                float rhi = __shfl_xor_sync(0xffffffffu, shi, 1);
                float iv = odd ? rlo : a0;
                float fv = odd ? rhi : a1;
                float gv = odd ? a2 : rlo;
                float ov = odd ? a3 : rhi;
                int rlocal = rbase + (odd ? 8 : 0);
                float cp = FIRST ? cp_sh : cbuf[rlocal * EPI_STRIDE + klocal];
                float cn = fsig(fv) * cp + fsig(iv) * ftanh(gv);
                float h = fsig(ov) * ftanh(cn);
                hbuf[rlocal * EPI_STRIDE + klocal] = h;
                hb16[rlocal * HB_STRIDE + klocal] = __float2half(h);
                if (FIRST) cbuf[rlocal * EPI_STRIDE + klocal] = cn;
            }
        }
    }
    __syncthreads();

    {   // coalesced writeout of the 128x64 h tile
        int r = tid >> 2, kh = (tid & 3) * 16;
        int row = bm + r;
        int kg = kb0 + kh;
#pragma unroll
        for (int j = 0; j < 4; j++) {
            const float* hsrc = &hbuf[r * EPI_STRIDE + kh + 4 * j];
            float4 v = make_float4(hsrc[0], hsrc[1], hsrc[2], hsrc[3]);
            if (FIRST) {
                __half2 p0 = __floats2half2_rn(v.x, v.y);
                __half2 p1 = __floats2half2_rn(v.z, v.w);
                uint2 u; u.x = *(uint32_t*)&p0; u.y = *(uint32_t*)&p1;
                *(uint2*)(d_xh + (size_t)row * KA + kg + 4 * j) = u;
                const float* csrc = &cbuf[r * EPI_STRIDE + kh + 4 * j];
                float4 cv = make_float4(csrc[0], csrc[1], csrc[2], csrc[3]);
                *(float4*)(d_c + (size_t)row * HH + kg + 4 * j) = cv;
            } else {
                *(float4*)(out + (size_t)row * K2 + kg + 4 * j) = v;
            }
        }
    }

    {   // ---- u partial: upart[q] = h_tile(128x64k) @ Wmth(128d x HHk)^T ----
        // warp mapping for d: wn2 = (warp>>1)*16, 2 n-tiles of 8 -> d < 128
        const int wn2 = (warp >> 1) * 16;
        float uacc[4][2][4];
#pragma unroll
        for (int a = 0; a < 4; a++)
#pragma unroll
            for (int b = 0; b < 2; b++)
#pragma unroll
                for (int c = 0; c < 4; c++) uacc[a][b][c] = 0.0f;
#pragma unroll
        for (int kt = 0; kt < 4; kt++) {
            int kloc = kt * 16 + 2 * t;
            unsigned af[4][4], bf[2][2];
#pragma unroll
            for (int mi = 0; mi < 4; mi++) {
                const __half* ba = &hb16[(wm + mi * 16 + g) * HB_STRIDE + kloc];
                af[mi][0] = *(const uint32_t*)(ba);
                af[mi][1] = *(const uint32_t*)(ba + 8 * HB_STRIDE);
                af[mi][2] = *(const uint32_t*)(ba + 8);
                af[mi][3] = *(const uint32_t*)(ba + 8 * HB_STRIDE + 8);
            }
#pragma unroll
            for (int ni = 0; ni < 2; ni++) {
                const __half* bb = &d_Wmth[(size_t)(wn2 + ni * 8 + g) * HH + kb0 + kloc];
                bf[ni][0] = *(const uint32_t*)(bb);
                bf[ni][1] = *(const uint32_t*)(bb + 8);
            }
#pragma unroll
            for (int mi = 0; mi < 4; mi++)
#pragma unroll
                for (int ni = 0; ni < 2; ni++)
                    asm volatile(
                        "mma.sync.aligned.m16n8k16.row.col.f32.f16.f16.f32 "
                        "{%0,%1,%2,%3}, {%4,%5,%6,%7}, {%8,%9}, {%0,%1,%2,%3};"
                        : "+f"(uacc[mi][ni][0]), "+f"(uacc[mi][ni][1]),
                          "+f"(uacc[mi][ni][2]), "+f"(uacc[mi][ni][3])
                        : "r"(af[mi][0]), "r"(af[mi][1]), "r"(af[mi][2]), "r"(af[mi][3]),
                          "r"(bf[ni][0]), "r"(bf[ni][1]));
        }
        float* up = d_upart + (size_t)q * GG * DD;
#pragma unroll
        for (int mi = 0; mi < 4; mi++) {
            int r0 = bm + wm + mi * 16 + g;
#pragma unroll
            for (int ni = 0; ni < 2; ni++) {
                int dd = wn2 + ni * 8 + 2 * t;
                *(float2*)&up[(size_t)r0 * DD + dd] =
                    make_float2(uacc[mi][ni][0], uacc[mi][ni][1]);
                *(float2*)&up[(size_t)(r0 + 8) * DD + dd] =
                    make_float2(uacc[mi][ni][2], uacc[mi][ni][3]);
            }
        }
    }

    if (tid < 128) {   // ---- beta partial: b_m[kslice] . h[g] ----
        float p = 0.0f;
#pragma unroll
        for (int k = 0; k < 64; k++)
            p += __half2float(hb16[tid * HB_STRIDE + k]) * b_m[kb0 + k];
        d_bpart[q * GG + bm + tid] = p;
    }
}

// ------- fused attention; blocks >= GG (t=0 launch only) compute gbias -------
__global__ __launch_bounds__(256) void attention_fused(int use_u0) {
    int g = blockIdx.x;
    int tid = threadIdx.x, lane = tid & 31, warp = tid >> 5;
    if (g >= GG) {
        int base = (g - GG) * 16 + warp * 2;
#pragma unroll
        for (int r = 0; r < 2; r++) {
            int nj = base + r;
            const __half2* w2 = (const __half2*)(d_Wch + (size_t)nj * KA);
            const float2* h02 = (const float2*)d_h0;
            float p = 0.0f;
#pragma unroll
            for (int i = lane; i < HH / 2; i += 32) {
                float2 wf = __half22float2(w2[i]);
                float2 hf = h02[i];
                p += wf.x * hf.x + wf.y * hf.y;
            }
            p += __shfl_xor_sync(0xffffffffu, p, 16);
            p += __shfl_xor_sync(0xffffffffu, p, 8);
            p += __shfl_xor_sync(0xffffffffu, p, 4);
            p += __shfl_xor_sync(0xffffffffu, p, 2);
            p += __shfl_xor_sync(0xffffffffu, p, 1);
            if (lane == 0) d_gbias4f[nj] = d_bias4f[nj] + p;
        }
        return;
    }
    int s0 = d_start[g], s1 = d_start[g + 1];
    __shared__ __align__(16) float u_s[128];
    __shared__ __align__(16) float wacc[8][128];
    __shared__ float wm_s[8], wS_s[8], fac_s[8];
    __shared__ float inv_s, beta_s;

    if (tid < 128) {
        if (use_u0) {
            u_s[tid] = d_u0[tid];
        } else {
            float s = 0.0f;
#pragma unroll
            for (int qq = 0; qq < 8; qq++)
                s += d_upart[((size_t)qq * GG + g) * DD + tid];
            u_s[tid] = s;
        }
    }
    if (tid == 0) {
        if (use_u0) {
            beta_s = d_beta0[0];
        } else {
            float bsum = 0.0f;
#pragma unroll
            for (int qq = 0; qq < 8; qq++) bsum += d_bpart[qq * GG + g];
            beta_s = bsum;
        }
    }
    __syncthreads();
    float beta = beta_s;

    float4 uv = ((const float4*)u_s)[lane];
    float m = -3.4e38f, S = 0.0f;
    float4 acc = make_float4(0.f, 0.f, 0.f, 0.f);

    for (int base = s0 + warp * 4; base < s1; base += 32) {
        float4 fv[4];
        float e[4];
#pragma unroll
        for (int j = 0; j < 4; j++) {
            int n = base + j;
            if (n < s1) {
                uint2 raw = *(const uint2*)(d_fh + (size_t)n * DD + lane * 4);
                float2 f01 = __half22float2(*(__half2*)&raw.x);
                float2 f23 = __half22float2(*(__half2*)&raw.y);
                fv[j] = make_float4(f01.x, f01.y, f23.x, f23.y);
            } else {
                fv[j] = make_float4(0.f, 0.f, 0.f, 0.f);
            }
            e[j] = fv[j].x * uv.x + fv[j].y * uv.y + fv[j].z * uv.z + fv[j].w * uv.w;
        }
#pragma unroll
        for (int j = 0; j < 4; j++) {
            e[j] += __shfl_xor_sync(0xffffffffu, e[j], 16);
            e[j] += __shfl_xor_sync(0xffffffffu, e[j], 8);
            e[j] += __shfl_xor_sync(0xffffffffu, e[j], 4);
            e[j] += __shfl_xor_sync(0xffffffffu, e[j], 2);
            e[j] += __shfl_xor_sync(0xffffffffu, e[j], 1);
        }
#pragma unroll
        for (int j = 0; j < 4; j++)
            e[j] = (base + j < s1) ? e[j] + beta : -3.0e38f;

        float m4 = fmaxf(fmaxf(e[0], e[1]), fmaxf(e[2], e[3]));
        float w0 = __expf(e[0] - m4), w1 = __expf(e[1] - m4);
        float w2 = __expf(e[2] - m4), w3 = __expf(e[3] - m4);
        float S4 = (w0 + w1) + (w2 + w3);
        float4 a4;
        a4.x = w0 * fv[0].x + w1 * fv[1].x + w2 * fv[2].x + w3 * fv[3].x;
        a4.y = w0 * fv[0].y + w1 * fv[1].y + w2 * fv[2].y + w3 * fv[3].y;
        a4.z = w0 * fv[0].z + w1 * fv[1].z + w2 * fv[2].z + w3 * fv[3].z;
        a4.w = w0 * fv[0].w + w1 * fv[1].w + w2 * fv[2].w + w3 * fv[3].w;

        float mn = fmaxf(m, m4);
        float al = __expf(m - mn);
        float bl = __expf(m4 - mn);
        S = S * al + S4 * bl;
        acc.x = acc.x * al + a4.x * bl;
        acc.y = acc.y * al + a4.y * bl;
        acc.z = acc.z * al + a4.z * bl;
        acc.w = acc.w * al + a4.w * bl;
        m = mn;
    }
    if (lane == 0) { wm_s[warp] = m; wS_s[warp] = S; }
    ((float4*)wacc[warp])[lane] = acc;
    __syncthreads();

    if (tid == 0) {
        float M = -3.4e38f;
#pragma unroll
        for (int w = 0; w < 8; w++)
            if (wS_s[w] > 0.0f) M = fmaxf(M, wm_s[w]);
        float Z = 0.0f;
#pragma unroll
        for (int w = 0; w < 8; w++) {
            float sc = (wS_s[w] > 0.0f) ? __expf(wm_s[w] - M) : 0.0f;
            fac_s[w] = sc;
            Z += sc * wS_s[w];
        }
        float inv = 1.0f / (Z + 1e-7f);
        inv_s = inv;
        d_tg[g] = Z * inv;
    }
    __syncthreads();

    if (tid < 128) {
        float inv = inv_s;
        float s = 0.0f;
#pragma unroll
        for (int w = 0; w < 8; w++) s += wacc[w][tid] * fac_s[w];
        s *= inv;
        d_s[g * DD + tid] = s;
        d_xh[(size_t)g * KA + 512 + tid] = __float2half(s);   // fp16 A operand
    }
}

// -------- final r output: r_g = W_m s_g + t_g b_m  (8 graphs / block) --------
__global__ __launch_bounds__(512) void compute_r(const float* __restrict__ b_m,
                                                 float* __restrict__ out) {
    int g0 = blockIdx.x * 8;
    int k = threadIdx.x;                              // 0..511
    __shared__ float ss[8][128];
    {
        int i = k;        ss[i >> 7][i & 127] = d_s[(g0 + (i >> 7)) * DD + (i & 127)];
        int i2 = k + 512; ss[i2 >> 7][i2 & 127] = d_s[(g0 + (i2 >> 7)) * DD + (i2 & 127)];
    }
    __syncthreads();
    float bm = b_m[k];
    float acc[8];
#pragma unroll
    for (int gg = 0; gg < 8; gg++) acc[gg] = d_tg[g0 + gg] * bm;
    for (int d = 0; d < DD; d++) {
        float w = d_Wmt[d * HH + k];
#pragma unroll
        for (int gg = 0; gg < 8; gg++) acc[gg] += w * ss[gg][d];
    }
#pragma unroll
    for (int gg = 0; gg < 8; gg++)
        out[(g0 + gg) * K2 + HH + k] = acc[gg];
}

// ------------------------------ launcher ------------------------------------
extern "C" void kernel_launch(void* const* d_in, const int* in_sizes, int n_in,
                              void* d_out, int out_size) {
    const float* features = (const float*)d_in[0];
    const int*   gi       = (const int*)d_in[1];
    const float* W_m      = (const float*)d_in[2];
    const float* b_m      = (const float*)d_in[3];
    const float* W_ih     = (const float*)d_in[4];
    const float* W_hh     = (const float*)d_in[5];
    const float* b_ih     = (const float*)d_in[6];
    const float* b_hh     = (const float*)d_in[7];
    float* out = (float*)d_out;

    cudaFuncSetAttribute(gemm_lstm<512, 128, true>,
                         cudaFuncAttributeMaxDynamicSharedMemorySize, GEMM_SMEM);
    cudaFuncSetAttribute(gemm_lstm<0, 640, false>,
                         cudaFuncAttributeMaxDynamicSharedMemorySize, GEMM_SMEM);

    prep_all<<<PREP_BLOCKS, 256, PREP_SMEM>>>(features, W_ih, W_hh, b_ih, b_hh,
                                              W_m, b_m, gi);

    // t = 0: shared u0/beta0; extra blocks compute gbias
    attention_fused<<<GG + 128, 256>>>(1);

    // t = 1: K=128 GEMM over s0; LSTM + u/beta partials in epilogue
    gemm_lstm<512, 128, true><<<dim3(H4 / 256, GG / 128), 512, GEMM_SMEM>>>(out, b_m);
    attention_fused<<<GG, 256>>>(0);

    // t = 2: K=640 GEMM over [h1 | s1]; epilogue writes final h + partials
    gemm_lstm<0, 640, false><<<dim3(H4 / 256, GG / 128), 512, GEMM_SMEM>>>(out, b_m);
    attention_fused<<<GG, 256>>>(0);
    compute_r<<<256, 512>>>(b_m, out);
}

// round 15
// speedup vs baseline: 1.9062x; 1.0645x over previous
#include <cuda_runtime.h>
#include <cuda_fp16.h>
#include <cstdint>
#include <math.h>

// Problem constants (fixed instance)
#define NN 131072   // nodes
#define DD 128      // feature dim
#define GG 2048     // graphs
#define HH 512      // hidden
#define H4 2048     // 4*H
#define K2 1024     // output q_star stride (2H)
#define KA 640      // GEMM K stride: [h(512) | s(128)]

// ---------------- scratch (static device globals; no allocation) -------------
__device__ __half d_Wch[H4 * KA];      // rows permuted nj=4k+gate: [Wc_h | Wrm]
__device__ float d_bias4f[H4];         // permuted bias: [k*4+gate]
__device__ float d_gbias4f[H4];        // permuted bias + h0 contribution (t=1)
__device__ float d_vb4f[H4];           // permuted vb = Wih_r @ b_m
__device__ float d_Wmt[DD * HH];       // W_m transposed (fp32, compute_r)
__device__ __half d_Wmth[DD * HH];     // W_m transposed fp16 (epilogue u-mma)
__device__ __half d_xh[GG * KA];       // fp16 A operand: [h | s] per graph
__device__ float d_c[GG * HH];         // LSTM cell state (t=1 -> t=2)
__device__ float d_h0[HH];             // shared h after t=0
__device__ float d_c0[HH];             // shared c after t=0
__device__ float d_u0[DD];             // shared u after t=0
__device__ float d_beta0[1];           // shared beta after t=0
__device__ float d_upart[8 * GG * DD]; // u partials per k-slice q
__device__ float d_bpart[8 * GG];      // beta partials per k-slice q
__device__ float d_s[GG * DD];         // s_g fp32 (final compute_r)
__device__ float d_tg[GG];             // exp_sum/(exp_sum+eps)
__device__ int   d_start[GG + 1];      // segment offsets

__device__ __forceinline__ float fsig(float x) {
    return __fdividef(1.0f, 1.0f + __expf(-x));
}
__device__ __forceinline__ float ftanh(float x) {
    return __fdividef(2.0f, 1.0f + __expf(-2.0f * x)) - 1.0f;
}
__device__ __forceinline__ int njperm(int j) { return 4 * (j & 511) + (j >> 9); }

// ---------------- prep_all: everything independent, one launch ---------------
#define B_WCH  4096
#define B_WRM  128
#define B_WMT  256
#define B_B4   2
#define B_VB   256
#define B_OFF  9
#define PREP_BLOCKS (B_WCH + B_WRM + B_WMT + B_B4 + B_VB + B_OFF + 1)
#define PREP_SMEM 49152

__global__ __launch_bounds__(256) void prep_all(
    const float* __restrict__ W_ih,
    const float* __restrict__ W_hh, const float* __restrict__ b_ih,
    const float* __restrict__ b_hh, const float* __restrict__ W_m,
    const float* __restrict__ b_m, const int* __restrict__ gi) {
    extern __shared__ float sm[];
    int b = blockIdx.x;
    int tid = threadIdx.x;
    if (b < B_WCH) {                        // Wc_h = W_ih[:, :512]+W_hh, permuted
        int idx = b * 256 + tid;
        int j = idx >> 9, col = idx & 511;
        float v = W_ih[(size_t)j * 1024 + col] + W_hh[(size_t)j * HH + col];
        d_Wch[(size_t)njperm(j) * KA + col] = __float2half(v);
        return;
    }
    b -= B_WCH;
    if (b < B_WRM) {                        // Wrm[j,d] = Wih_r[j,:] . W_m[:,d]
        float* wr_s = sm;                   // [16][512]
        float* red  = sm + 8192;            // [2][16][128]
        int j0 = b * 16;
        for (int idx = tid; idx < 16 * HH; idx += 256) {
            int jj = idx >> 9, k = idx & 511;
            wr_s[idx] = W_ih[(size_t)(j0 + jj) * 1024 + 512 + k];
        }
        __syncthreads();
        int d = tid & 127, kh = tid >> 7;
        int kb = kh * 256;
        float acc[16];
#pragma unroll
        for (int jj = 0; jj < 16; jj++) acc[jj] = 0.0f;
        for (int k = 0; k < 256; k++) {
            float w = W_m[(size_t)(kb + k) * DD + d];
#pragma unroll
            for (int jj = 0; jj < 16; jj++)
                acc[jj] += w * wr_s[jj * HH + kb + k];
        }
#pragma unroll
        for (int jj = 0; jj < 16; jj++) red[(kh * 16 + jj) * 128 + d] = acc[jj];
        __syncthreads();
#pragma unroll
        for (int q = 0; q < 8; q++) {
            int e = tid + q * 256;
            int jj = e >> 7, dd = e & 127;
            float v = red[jj * 128 + dd] + red[(16 + jj) * 128 + dd];
            d_Wch[(size_t)njperm(j0 + jj) * KA + 512 + dd] = __float2half(v);
        }
        return;
    }
    b -= B_WRM;
    if (b < B_WMT) {                        // W_m transposed fp32 + fp16
        int idx = b * 256 + tid;
        int d = idx >> 9, k = idx & 511;
        float v = W_m[k * DD + d];
        d_Wmt[idx] = v;
        d_Wmth[idx] = __float2half(v);
        return;
    }
    b -= B_WMT;
    if (b < B_B4) {                         // permuted bias float4 per k
        int k = b * 256 + tid;
        float4 v;
        v.x = b_ih[k] + b_hh[k];
        v.y = b_ih[HH + k] + b_hh[HH + k];
        v.z = b_ih[2 * HH + k] + b_hh[2 * HH + k];
        v.w = b_ih[3 * HH + k] + b_hh[3 * HH + k];
        ((float4*)d_bias4f)[k] = v;
        return;
    }
    b -= B_B4;
    if (b < B_VB) {                         // vb[j] = Wih_r[j,:] . b_m
        int w = tid >> 5, lane = tid & 31;
        int j = b * 8 + w;
        const float* wr = W_ih + (size_t)j * 1024 + 512;
        float p = 0.0f;
#pragma unroll
        for (int k = lane; k < HH; k += 32) p += wr[k] * b_m[k];
        p += __shfl_xor_sync(0xffffffffu, p, 16);
        p += __shfl_xor_sync(0xffffffffu, p, 8);
        p += __shfl_xor_sync(0xffffffffu, p, 4);
        p += __shfl_xor_sync(0xffffffffu, p, 2);
        p += __shfl_xor_sync(0xffffffffu, p, 1);
        if (lane == 0) d_vb4f[njperm(j)] = p;
        return;
    }
    b -= B_VB;
    if (b < B_OFF) {                        // segment offsets (sorted index)
        int g = b * 256 + tid;
        if (g > GG) return;
        int lo = 0, hi = NN;
        while (lo < hi) { int mid = (lo + hi) >> 1; if (gi[mid] < g) lo = mid + 1; else hi = mid; }
        d_start[g] = lo;
        return;
    }
    // ---- init0 ----
    {
        float* h_s = sm;
        float* br  = sm + 512;
        float bsum = 0.0f;
#pragma unroll
        for (int q = 0; q < 2; q++) {
            int k = tid + q * 256;
            float big = b_ih[k] + b_hh[k];
            float bgg = b_ih[2 * HH + k] + b_hh[2 * HH + k];
            float bog = b_ih[3 * HH + k] + b_hh[3 * HH + k];
            float c = fsig(big) * ftanh(bgg);
            float h = fsig(bog) * ftanh(c);
            h_s[k] = h;
            d_h0[k] = h;
            d_c0[k] = c;
            bsum += b_m[k] * h;
        }
        br[tid] = bsum;
        __syncthreads();
        if (tid < DD) {
            float a = 0.0f;
            for (int k = 0; k < HH; k++) a += W_m[k * DD + tid] * h_s[k];
            d_u0[tid] = a;
        }
        for (int s = 128; s > 0; s >>= 1) {
            if (tid < s) br[tid] += br[tid + s];
            __syncthreads();
        }
        if (tid == 0) d_beta0[0] = br[0];
    }
}

// ------ gates GEMM + fused LSTM + fused u/beta partial epilogue --------------
#define SROWH 40
#define A_STGH (128 * SROWH)
#define B_STGH (256 * SROWH)
#define EPI_STRIDE 68
#define HB_STRIDE 72
#define GEMM_SMEM (2 * 128 * EPI_STRIDE * 4 + 512 + 128 * HB_STRIDE * 2)

__device__ __forceinline__ void cpa16(uint32_t daddr, const void* g) {
    asm volatile("cp.async.cg.shared.global [%0], [%1], 16;" :: "r"(daddr), "l"(g));
}

__device__ __forceinline__ void load_stage(uint32_t sA, uint32_t sB,
                                           int bm, int bn, int k0, int tid) {
    {
        int row = tid >> 2, c = tid & 3;
        cpa16(sA + (uint32_t)(row * SROWH + c * 8) * 2,
              d_xh + (size_t)(bm + row) * KA + k0 + c * 8);
    }
#pragma unroll
    for (int j = 0; j < 2; j++) {
        int b = tid + j * 512;
        int row = b >> 2, c = b & 3;
        cpa16(sB + (uint32_t)(row * SROWH + c * 8) * 2,
              d_Wch + (size_t)(bn + row) * KA + k0 + c * 8);
    }
    asm volatile("cp.async.commit_group;");
}

template <int KOFF, int KLEN, bool FIRST>
__global__ __launch_bounds__(512, 1) void gemm_lstm(float* __restrict__ out,
                                                    const float* __restrict__ b_m) {
    extern __shared__ __half smh[];
    __half* Abase = smh;
    __half* Bbase = smh + 2 * A_STGH;
    uint32_t sAu, sBu;
    {
        uint64_t t;
        asm("cvta.to.shared.u64 %0, %1;" : "=l"(t) : "l"(Abase));
        sAu = (uint32_t)t;
        asm("cvta.to.shared.u64 %0, %1;" : "=l"(t) : "l"(Bbase));
        sBu = (uint32_t)t;
    }
    const int tid = threadIdx.x, lane = tid & 31, warp = tid >> 5;
    const int wm = (warp & 1) * 64, wn = (warp >> 1) * 32;
    const int g = lane >> 2, t = lane & 3;
    const int bm = blockIdx.y * 128, bn = blockIdx.x * 256;
    const int q = blockIdx.x;                        // k-slice index 0..7

    float acc[4][4][4];
#pragma unroll
    for (int a = 0; a < 4; a++)
#pragma unroll
        for (int b = 0; b < 4; b++)
#pragma unroll
            for (int c = 0; c < 4; c++) acc[a][b][c] = 0.0f;

    load_stage(sAu, sBu, bm, bn, KOFF, tid);

    const int NIT = KLEN / 32;
    for (int it = 0; it < NIT; it++) {
        int buf = it & 1;
        if (it + 1 < NIT) {
            int nb = buf ^ 1;
            load_stage(sAu + nb * A_STGH * 2, sBu + nb * B_STGH * 2,
                       bm, bn, KOFF + (it + 1) * 32, tid);
            asm volatile("cp.async.wait_group 1;");
        } else {
            asm volatile("cp.async.wait_group 0;");
        }
        __syncthreads();

        const __half* Ab = Abase + buf * A_STGH;
        const __half* Bb = Bbase + buf * B_STGH;
#pragma unroll
        for (int kb = 0; kb < 32; kb += 16) {
            unsigned af[4][4], bf[4][2];
#pragma unroll
            for (int mi = 0; mi < 4; mi++) {
                const __half* ba = &Ab[(wm + mi * 16 + g) * SROWH + kb + 2 * t];
                af[mi][0] = *(const uint32_t*)(ba);
                af[mi][1] = *(const uint32_t*)(ba + 8 * SROWH);
                af[mi][2] = *(const uint32_t*)(ba + 8);
                af[mi][3] = *(const uint32_t*)(ba + 8 * SROWH + 8);
            }
#pragma unroll
            for (int ni = 0; ni < 4; ni++) {
                const __half* bb = &Bb[(wn + ni * 8 + g) * SROWH + kb + 2 * t];
                bf[ni][0] = *(const uint32_t*)(bb);
                bf[ni][1] = *(const uint32_t*)(bb + 8);
            }
#pragma unroll
            for (int mi = 0; mi < 4; mi++)
#pragma unroll
                for (int ni = 0; ni < 4; ni++)
                    asm volatile(
                        "mma.sync.aligned.m16n8k16.row.col.f32.f16.f16.f32 "
                        "{%0,%1,%2,%3}, {%4,%5,%6,%7}, {%8,%9}, {%0,%1,%2,%3};"
                        : "+f"(acc[mi][ni][0]), "+f"(acc[mi][ni][1]),
                          "+f"(acc[mi][ni][2]), "+f"(acc[mi][ni][3])
                        : "r"(af[mi][0]), "r"(af[mi][1]), "r"(af[mi][2]), "r"(af[mi][3]),
                          "r"(bf[ni][0]), "r"(bf[ni][1]));
        }
        __syncthreads();
    }

    // ---------------- fused LSTM epilogue ----------------
    float* hbuf = (float*)smh;                       // [128][EPI_STRIDE] fp32 h
    float* cbuf = hbuf + 128 * EPI_STRIDE;           // [128][EPI_STRIDE] c
    float* tgs  = cbuf + 128 * EPI_STRIDE;           // [128]
    __half* hb16 = (__half*)(tgs + 128);             // [128][HB_STRIDE] fp16 h
    const int kb0 = bn >> 2;                         // first k of CTA tile
    const float4* b4p = (const float4*)(FIRST ? d_gbias4f : d_bias4f);
    const float4* vb4p = (const float4*)d_vb4f;

    if (tid < 128) tgs[tid] = d_tg[bm + tid];
    if (!FIRST) {                                    // preload c tile, coalesced
        int r = tid >> 2, kh = (tid & 3) * 16;
        const float4* src = (const float4*)(d_c + (size_t)(bm + r) * HH + kb0 + kh);
#pragma unroll
        for (int j = 0; j < 4; j++) {
            float4 v = src[j];
            float* dst = &cbuf[r * EPI_STRIDE + kh + 4 * j];
            dst[0] = v.x; dst[1] = v.y; dst[2] = v.z; dst[3] = v.w;
        }
    }
    __syncthreads();

    {
        const int kwarp = (bn + wn) >> 2;
        const bool odd = t & 1;
        const int khalf = t >> 1;
#pragma unroll
        for (int ni = 0; ni < 4; ni++) {
            int k = kwarp + ni * 2 + khalf;
            float4 b4 = b4p[k];
            float4 v4 = vb4p[k];
            float blo = odd ? b4.z : b4.x;
            float bhi = odd ? b4.w : b4.y;
            float vlo = odd ? v4.z : v4.x;
            float vhi = odd ? v4.w : v4.y;
            float cp_sh = FIRST ? d_c0[k] : 0.0f;
            int klocal = k - kb0;
#pragma unroll
            for (int mi = 0; mi < 4; mi++) {
                int rbase = wm + mi * 16 + g;
                float tg0 = tgs[rbase];
                float tg1 = tgs[rbase + 8];
                float a0 = acc[mi][ni][0] + blo + tg0 * vlo;
                float a1 = acc[mi][ni][1] + bhi + tg0 * vhi;
                float a2 = acc[mi][ni][2] + blo + tg1 * vlo;
                float a3 = acc[mi][ni][3] + bhi + tg1 * vhi;
                float slo = odd ? a0 : a2;
                float shi = odd ? a1 : a3;
                float rlo = __shfl_xor_sync(0xffffffffu, slo, 1);
                float rhi = __shfl_xor_sync(0xffffffffu, shi, 1);
                float iv = odd ? rlo : a0;
                float fv = odd ? rhi : a1;
                float gv = odd ? a2 : rlo;
                float ov = odd ? a3 : rhi;
                int rlocal = rbase + (odd ? 8 : 0);
                float cp = FIRST ? cp_sh : cbuf[rlocal * EPI_STRIDE + klocal];
                float cn = fsig(fv) * cp + fsig(iv) * ftanh(gv);
                float h = fsig(ov) * ftanh(cn);
                hbuf[rlocal * EPI_STRIDE + klocal] = h;
                hb16[rlocal * HB_STRIDE + klocal] = __float2half(h);
                if (FIRST) cbuf[rlocal * EPI_STRIDE + klocal] = cn;
            }
        }
    }
    __syncthreads();

    {   // coalesced writeout of the 128x64 h tile
        int r = tid >> 2, kh = (tid & 3) * 16;
        int row = bm + r;
        int kg = kb0 + kh;
#pragma unroll
        for (int j = 0; j < 4; j++) {
            const float* hsrc = &hbuf[r * EPI_STRIDE + kh + 4 * j];
            float4 v = make_float4(hsrc[0], hsrc[1], hsrc[2], hsrc[3]);
            if (FIRST) {
                __half2 p0 = __floats2half2_rn(v.x, v.y);
                __half2 p1 = __floats2half2_rn(v.z, v.w);
                uint2 u; u.x = *(uint32_t*)&p0; u.y = *(uint32_t*)&p1;
                *(uint2*)(d_xh + (size_t)row * KA + kg + 4 * j) = u;
                const float* csrc = &cbuf[r * EPI_STRIDE + kh + 4 * j];
                float4 cv = make_float4(csrc[0], csrc[1], csrc[2], csrc[3]);
                *(float4*)(d_c + (size_t)row * HH + kg + 4 * j) = cv;
            } else {
                *(float4*)(out + (size_t)row * K2 + kg + 4 * j) = v;
            }
        }
    }

    {   // ---- u partial: upart[q] = h_tile(128x64k) @ Wmth(128d x HHk)^T ----
        const int wn2 = (warp >> 1) * 16;            // d mapping: < 128
        float uacc[4][2][4];
#pragma unroll
        for (int a = 0; a < 4; a++)
#pragma unroll
            for (int b = 0; b < 2; b++)
#pragma unroll
                for (int c = 0; c < 4; c++) uacc[a][b][c] = 0.0f;
#pragma unroll
        for (int kt = 0; kt < 4; kt++) {
            int kloc = kt * 16 + 2 * t;
            unsigned af[4][4], bf[2][2];
#pragma unroll
            for (int mi = 0; mi < 4; mi++) {
                const __half* ba = &hb16[(wm + mi * 16 + g) * HB_STRIDE + kloc];
                af[mi][0] = *(const uint32_t*)(ba);
                af[mi][1] = *(const uint32_t*)(ba + 8 * HB_STRIDE);
                af[mi][2] = *(const uint32_t*)(ba + 8);
                af[mi][3] = *(const uint32_t*)(ba + 8 * HB_STRIDE + 8);
            }
#pragma unroll
            for (int ni = 0; ni < 2; ni++) {
                const __half* bb = &d_Wmth[(size_t)(wn2 + ni * 8 + g) * HH + kb0 + kloc];
                bf[ni][0] = *(const uint32_t*)(bb);
                bf[ni][1] = *(const uint32_t*)(bb + 8);
            }
#pragma unroll
            for (int mi = 0; mi < 4; mi++)
#pragma unroll
                for (int ni = 0; ni < 2; ni++)
                    asm volatile(
                        "mma.sync.aligned.m16n8k16.row.col.f32.f16.f16.f32 "
                        "{%0,%1,%2,%3}, {%4,%5,%6,%7}, {%8,%9}, {%0,%1,%2,%3};"
                        : "+f"(uacc[mi][ni][0]), "+f"(uacc[mi][ni][1]),
                          "+f"(uacc[mi][ni][2]), "+f"(uacc[mi][ni][3])
                        : "r"(af[mi][0]), "r"(af[mi][1]), "r"(af[mi][2]), "r"(af[mi][3]),
                          "r"(bf[ni][0]), "r"(bf[ni][1]));
        }
        float* up = d_upart + (size_t)q * GG * DD;
#pragma unroll
        for (int mi = 0; mi < 4; mi++) {
            int r0 = bm + wm + mi * 16 + g;
#pragma unroll
            for (int ni = 0; ni < 2; ni++) {
                int dd = wn2 + ni * 8 + 2 * t;
                *(float2*)&up[(size_t)r0 * DD + dd] =
                    make_float2(uacc[mi][ni][0], uacc[mi][ni][1]);
                *(float2*)&up[(size_t)(r0 + 8) * DD + dd] =
                    make_float2(uacc[mi][ni][2], uacc[mi][ni][3]);
            }
        }
    }

    if (tid < 128) {   // ---- beta partial: b_m[kslice] . h[g] ----
        float p = 0.0f;
#pragma unroll
        for (int k = 0; k < 64; k++)
            p += __half2float(hb16[tid * HB_STRIDE + k]) * b_m[kb0 + k];
        d_bpart[q * GG + bm + tid] = p;
    }
}

// ------- fused attention (fp32 features); blocks >= GG compute gbias ---------
__global__ __launch_bounds__(256) void attention_fused(const float* __restrict__ f,
                                                       int use_u0) {
    int g = blockIdx.x;
    int tid = threadIdx.x, lane = tid & 31, warp = tid >> 5;
    if (g >= GG) {
        int base = (g - GG) * 16 + warp * 2;
#pragma unroll
        for (int r = 0; r < 2; r++) {
            int nj = base + r;
            const __half2* w2 = (const __half2*)(d_Wch + (size_t)nj * KA);
            const float2* h02 = (const float2*)d_h0;
            float p = 0.0f;
#pragma unroll
            for (int i = lane; i < HH / 2; i += 32) {
                float2 wf = __half22float2(w2[i]);
                float2 hf = h02[i];
                p += wf.x * hf.x + wf.y * hf.y;
            }
            p += __shfl_xor_sync(0xffffffffu, p, 16);
            p += __shfl_xor_sync(0xffffffffu, p, 8);
            p += __shfl_xor_sync(0xffffffffu, p, 4);
            p += __shfl_xor_sync(0xffffffffu, p, 2);
            p += __shfl_xor_sync(0xffffffffu, p, 1);
            if (lane == 0) d_gbias4f[nj] = d_bias4f[nj] + p;
        }
        return;
    }
    int s0 = d_start[g], s1 = d_start[g + 1];
    __shared__ __align__(16) float u_s[128];
    __shared__ __align__(16) float wacc[8][128];
    __shared__ float wm_s[8], wS_s[8], fac_s[8];
    __shared__ float inv_s, beta_s;

    if (tid < 128) {
        if (use_u0) {
            u_s[tid] = d_u0[tid];
        } else {
            float s = 0.0f;
#pragma unroll
            for (int qq = 0; qq < 8; qq++)
                s += d_upart[((size_t)qq * GG + g) * DD + tid];
            u_s[tid] = s;
        }
    }
    if (tid == 0) {
        if (use_u0) {
            beta_s = d_beta0[0];
        } else {
            float bsum = 0.0f;
#pragma unroll
            for (int qq = 0; qq < 8; qq++) bsum += d_bpart[qq * GG + g];
            beta_s = bsum;
        }
    }
    __syncthreads();
    float beta = beta_s;

    float4 uv = ((const float4*)u_s)[lane];
    float m = -3.4e38f, S = 0.0f;
    float4 acc = make_float4(0.f, 0.f, 0.f, 0.f);

    for (int base = s0 + warp * 4; base < s1; base += 32) {
        float4 fv[4];
        float e[4];
#pragma unroll
        for (int j = 0; j < 4; j++) {
            int n = base + j;
            if (n < s1) {
                fv[j] = *(const float4*)(f + (size_t)n * DD + lane * 4);
            } else {
                fv[j] = make_float4(0.f, 0.f, 0.f, 0.f);
            }
            e[j] = fv[j].x * uv.x + fv[j].y * uv.y + fv[j].z * uv.z + fv[j].w * uv.w;
        }
#pragma unroll
        for (int j = 0; j < 4; j++) {
            e[j] += __shfl_xor_sync(0xffffffffu, e[j], 16);
            e[j] += __shfl_xor_sync(0xffffffffu, e[j], 8);
            e[j] += __shfl_xor_sync(0xffffffffu, e[j], 4);
            e[j] += __shfl_xor_sync(0xffffffffu, e[j], 2);
            e[j] += __shfl_xor_sync(0xffffffffu, e[j], 1);
        }
#pragma unroll
        for (int j = 0; j < 4; j++)
            e[j] = (base + j < s1) ? e[j] + beta : -3.0e38f;

        float m4 = fmaxf(fmaxf(e[0], e[1]), fmaxf(e[2], e[3]));
        float w0 = __expf(e[0] - m4), w1 = __expf(e[1] - m4);
        float w2 = __expf(e[2] - m4), w3 = __expf(e[3] - m4);
        float S4 = (w0 + w1) + (w2 + w3);
        float4 a4;
        a4.x = w0 * fv[0].x + w1 * fv[1].x + w2 * fv[2].x + w3 * fv[3].x;
        a4.y = w0 * fv[0].y + w1 * fv[1].y + w2 * fv[2].y + w3 * fv[3].y;
        a4.z = w0 * fv[0].z + w1 * fv[1].z + w2 * fv[2].z + w3 * fv[3].z;
        a4.w = w0 * fv[0].w + w1 * fv[1].w + w2 * fv[2].w + w3 * fv[3].w;

        float mn = fmaxf(m, m4);
        float al = __expf(m - mn);
        float bl = __expf(m4 - mn);
        S = S * al + S4 * bl;
        acc.x = acc.x * al + a4.x * bl;
        acc.y = acc.y * al + a4.y * bl;
        acc.z = acc.z * al + a4.z * bl;
        acc.w = acc.w * al + a4.w * bl;
        m = mn;
    }
    if (lane == 0) { wm_s[warp] = m; wS_s[warp] = S; }
    ((float4*)wacc[warp])[lane] = acc;
    __syncthreads();

    if (tid == 0) {
        float M = -3.4e38f;
#pragma unroll
        for (int w = 0; w < 8; w++)
            if (wS_s[w] > 0.0f) M = fmaxf(M, wm_s[w]);
        float Z = 0.0f;
#pragma unroll
        for (int w = 0; w < 8; w++) {
            float sc = (wS_s[w] > 0.0f) ? __expf(wm_s[w] - M) : 0.0f;
            fac_s[w] = sc;
            Z += sc * wS_s[w];
        }
        float inv = 1.0f / (Z + 1e-7f);
        inv_s = inv;
        d_tg[g] = Z * inv;
    }
    __syncthreads();

    if (tid < 128) {
        float inv = inv_s;
        float s = 0.0f;
#pragma unroll
        for (int w = 0; w < 8; w++) s += wacc[w][tid] * fac_s[w];
        s *= inv;
        d_s[g * DD + tid] = s;
        d_xh[(size_t)g * KA + 512 + tid] = __float2half(s);   // fp16 A operand
    }
}

// -------- final r output: r_g = W_m s_g + t_g b_m  (8 graphs / block) --------
__global__ __launch_bounds__(512) void compute_r(const float* __restrict__ b_m,
                                                 float* __restrict__ out) {
    int g0 = blockIdx.x * 8;
    int k = threadIdx.x;                              // 0..511
    __shared__ float ss[8][128];
    {
        int i = k;        ss[i >> 7][i & 127] = d_s[(g0 + (i >> 7)) * DD + (i & 127)];
        int i2 = k + 512; ss[i2 >> 7][i2 & 127] = d_s[(g0 + (i2 >> 7)) * DD + (i2 & 127)];
    }
    __syncthreads();
    float bm = b_m[k];
    float acc[8];
#pragma unroll
    for (int gg = 0; gg < 8; gg++) acc[gg] = d_tg[g0 + gg] * bm;
    for (int d = 0; d < DD; d++) {
        float w = d_Wmt[d * HH + k];
#pragma unroll
        for (int gg = 0; gg < 8; gg++) acc[gg] += w * ss[gg][d];
    }
#pragma unroll
    for (int gg = 0; gg < 8; gg++)
        out[(g0 + gg) * K2 + HH + k] = acc[gg];
}

// ------------------------------ launcher ------------------------------------
extern "C" void kernel_launch(void* const* d_in, const int* in_sizes, int n_in,
                              void* d_out, int out_size) {
    const float* features = (const float*)d_in[0];
    const int*   gi       = (const int*)d_in[1];
    const float* W_m      = (const float*)d_in[2];
    const float* b_m      = (const float*)d_in[3];
    const float* W_ih     = (const float*)d_in[4];
    const float* W_hh     = (const float*)d_in[5];
    const float* b_ih     = (const float*)d_in[6];
    const float* b_hh     = (const float*)d_in[7];
    float* out = (float*)d_out;

    cudaFuncSetAttribute(gemm_lstm<512, 128, true>,
                         cudaFuncAttributeMaxDynamicSharedMemorySize, GEMM_SMEM);
    cudaFuncSetAttribute(gemm_lstm<0, 640, false>,
                         cudaFuncAttributeMaxDynamicSharedMemorySize, GEMM_SMEM);

    prep_all<<<PREP_BLOCKS, 256, PREP_SMEM>>>(W_ih, W_hh, b_ih, b_hh,
                                              W_m, b_m, gi);

    // t = 0: shared u0/beta0; extra blocks compute gbias
    attention_fused<<<GG + 128, 256>>>(features, 1);

    // t = 1: K=128 GEMM over s0; LSTM + u/beta partials in epilogue
    gemm_lstm<512, 128, true><<<dim3(H4 / 256, GG / 128), 512, GEMM_SMEM>>>(out, b_m);
    attention_fused<<<GG, 256>>>(features, 0);

    // t = 2: K=640 GEMM over [h1 | s1]; epilogue writes final h + partials
    gemm_lstm<0, 640, false><<<dim3(H4 / 256, GG / 128), 512, GEMM_SMEM>>>(out, b_m);
    attention_fused<<<GG, 256>>>(features, 0);
    compute_r<<<256, 512>>>(b_m, out);
}